// round 2
// baseline (speedup 1.0000x reference)
#include <cuda_runtime.h>
#include <cstdint>

// ---------------------------------------------------------------------------
// CompositionalMlp: grouped-by-expert GEMM pipeline, 3xTF32 mma.sync tensor path
// Scratch buffers selected device-side (no runtime API calls in kernel_launch).
// ---------------------------------------------------------------------------

#define BATCH  8192
#define NEXP   4
#define NTYPE  4
#define HDIM   512
#define NOUT   8
#define INW    144     // input_val row width
#define FEATW  32

#define BM 128
#define BN 128
#define KB 16
#define NTHREADS 256

// ---- scratch (static device memory; no allocations) -----------------------
__device__ int   g_idx[NTYPE][BATCH];
__device__ int   g_order[NTYPE][BATCH];
__device__ int   g_off[NTYPE][NEXP + 1];
__device__ int   g_cnt[NTYPE][NEXP];
__device__ int   g_pos[NTYPE][NEXP];
__device__ float g_bufA[BATCH * HDIM];
__device__ float g_bufB[BATCH * HDIM];
__device__ float g_bufH[BATCH * HDIM];

// buffer selectors: 0 = g_bufA, 1 = g_bufB, 2 = g_bufH, negative = use pointer arg
__device__ __forceinline__ float* scratch_ptr(int sel) {
    return sel == 0 ? g_bufA : (sel == 1 ? g_bufB : g_bufH);
}

// ---- helpers ---------------------------------------------------------------
__device__ __forceinline__ float tf32_rna(float v) {
    uint32_t u;
    asm("cvt.rna.tf32.f32 %0, %1;" : "=r"(u) : "f"(v));
    return __uint_as_float(u);
}

#define MMA_TF32(d, a, b0, b1)                                                \
    asm volatile(                                                             \
        "mma.sync.aligned.m16n8k8.row.col.f32.tf32.tf32.f32 "                 \
        "{%0,%1,%2,%3}, {%4,%5,%6,%7}, {%8,%9}, {%0,%1,%2,%3};\n"             \
        : "+f"((d)[0]), "+f"((d)[1]), "+f"((d)[2]), "+f"((d)[3])              \
        : "r"((a)[0]), "r"((a)[1]), "r"((a)[2]), "r"((a)[3]),                 \
          "r"(b0), "r"(b1))

// ---- prep kernels ----------------------------------------------------------
__global__ void prep_zero() {
    int t = threadIdx.x;
    if (t < NTYPE * NEXP) {
        ((int*)g_cnt)[t] = 0;
        ((int*)g_pos)[t] = 0;
    }
}

__global__ void prep_count(const float* __restrict__ in) {
    int b = blockIdx.x * blockDim.x + threadIdx.x;
    if (b >= BATCH) return;
    const float* oh = in + (size_t)b * INW + 4 * FEATW;
#pragma unroll
    for (int j = 0; j < NTYPE; j++) {
        int e = 0;
        float best = oh[j * NEXP];
#pragma unroll
        for (int m = 1; m < NEXP; m++) {
            float v = oh[j * NEXP + m];
            if (v > best) { best = v; e = m; }
        }
        g_idx[j][b] = e;
        atomicAdd(&g_cnt[j][e], 1);
    }
}

__global__ void prep_scan() {
    if (threadIdx.x == 0) {
#pragma unroll
        for (int j = 0; j < NTYPE; j++) {
            int s = 0;
#pragma unroll
            for (int e = 0; e < NEXP; e++) {
                g_off[j][e] = s;
                s += g_cnt[j][e];
            }
            g_off[j][NEXP] = s;
        }
    }
}

__global__ void prep_scatter() {
    int b = blockIdx.x * blockDim.x + threadIdx.x;
    if (b >= BATCH) return;
#pragma unroll
    for (int j = 0; j < NTYPE; j++) {
        int e = g_idx[j][b];
        int p = atomicAdd(&g_pos[j][e], 1);
        g_order[j][g_off[j][e] + p] = b;
    }
}

// ---- grouped GEMM: out[rows, 512] = relu(A[rows, K] @ W[e] + bias[e]) ------
// A is gathered per-row from A1 (cols [0,K1)) and optionally A2 (cols [K1,K)).
// A1/A2 come either from the external pointer (sel < 0) or a scratch buffer.
// 3xTF32: hi/lo split of both operands, drop lo*lo -> fp32-grade accuracy.
__global__ __launch_bounds__(NTHREADS)
void gemm_expert(const float* __restrict__ A1ext, int selA1, int lda1, int offA1, int K1,
                 int selA2, int K,
                 const float* __restrict__ W,      // [NEXP][K][512]
                 const float* __restrict__ bias,   // [NEXP][512]
                 int selOut,                        // scratch buffer for output
                 int jtype, int do_relu)
{
    __shared__ float Ahi[BM][KB + 1];
    __shared__ float Alo[BM][KB + 1];
    __shared__ float Whi[KB][BN + 4];
    __shared__ float Wlo[KB][BN + 4];
    __shared__ int   srow[BM];

    const float* A1 = (selA1 < 0) ? A1ext : scratch_ptr(selA1);
    const float* A2 = (selA2 < 0) ? nullptr : scratch_ptr(selA2);
    float*       out = scratch_ptr(selOut);
    const int lda2 = HDIM;

    const int e    = blockIdx.z;
    const int off  = g_off[jtype][e];
    const int cnt  = g_off[jtype][e + 1] - off;
    const int m0   = blockIdx.x * BM;
    if (m0 >= cnt) return;
    const int rows = min(BM, cnt - m0);
    const int n0   = blockIdx.y * BN;
    const int tid  = threadIdx.x;

    for (int i = tid; i < BM; i += NTHREADS)
        srow[i] = (i < rows) ? g_order[jtype][off + m0 + i] : -1;
    __syncthreads();

    const float* We = W + (size_t)e * K * HDIM;

    const int warp = tid >> 5, lane = tid & 31;
    const int wm = warp >> 1, wn = warp & 1;     // 4 x 2 warp grid
    const int gid = lane >> 2, tig = lane & 3;

    float acc[2][8][4];
#pragma unroll
    for (int mt = 0; mt < 2; mt++)
#pragma unroll
        for (int nt = 0; nt < 8; nt++)
#pragma unroll
            for (int q = 0; q < 4; q++) acc[mt][nt][q] = 0.f;

    for (int k0 = 0; k0 < K; k0 += KB) {
        // load + split A tile [BM x KB]
#pragma unroll
        for (int i = 0; i < (BM * KB) / NTHREADS; i++) {
            int flat = i * NTHREADS + tid;
            int r = flat >> 4;          // KB = 16
            int c = flat & 15;
            int k = k0 + c;
            float v = 0.f;
            int rowid = srow[r];
            if (rowid >= 0) {
                v = (k < K1) ? A1[(size_t)rowid * lda1 + offA1 + k]
                             : A2[(size_t)rowid * lda2 + (k - K1)];
            }
            float hi = tf32_rna(v);
            Ahi[r][c] = hi;
            Alo[r][c] = v - hi;
        }
        // load + split W tile [KB x BN]
#pragma unroll
        for (int i = 0; i < (KB * BN) / NTHREADS; i++) {
            int flat = i * NTHREADS + tid;
            int r = flat >> 7;          // BN = 128
            int c = flat & 127;
            float v = We[(size_t)(k0 + r) * HDIM + n0 + c];
            float hi = tf32_rna(v);
            Whi[r][c] = hi;
            Wlo[r][c] = v - hi;
        }
        __syncthreads();

#pragma unroll
        for (int ks = 0; ks < KB / 8; ks++) {
            const int kk = ks * 8;
            uint32_t ah[2][4], al[2][4];
#pragma unroll
            for (int mt = 0; mt < 2; mt++) {
                int rb = wm * 32 + mt * 16;
                ah[mt][0] = __float_as_uint(Ahi[rb + gid    ][kk + tig    ]);
                ah[mt][1] = __float_as_uint(Ahi[rb + gid + 8][kk + tig    ]);
                ah[mt][2] = __float_as_uint(Ahi[rb + gid    ][kk + tig + 4]);
                ah[mt][3] = __float_as_uint(Ahi[rb + gid + 8][kk + tig + 4]);
                al[mt][0] = __float_as_uint(Alo[rb + gid    ][kk + tig    ]);
                al[mt][1] = __float_as_uint(Alo[rb + gid + 8][kk + tig    ]);
                al[mt][2] = __float_as_uint(Alo[rb + gid    ][kk + tig + 4]);
                al[mt][3] = __float_as_uint(Alo[rb + gid + 8][kk + tig + 4]);
            }
#pragma unroll
            for (int nt = 0; nt < 8; nt++) {
                int cc = wn * 64 + nt * 8 + gid;
                uint32_t bh0 = __float_as_uint(Whi[kk + tig    ][cc]);
                uint32_t bh1 = __float_as_uint(Whi[kk + tig + 4][cc]);
                uint32_t bl0 = __float_as_uint(Wlo[kk + tig    ][cc]);
                uint32_t bl1 = __float_as_uint(Wlo[kk + tig + 4][cc]);
#pragma unroll
                for (int mt = 0; mt < 2; mt++) {
                    MMA_TF32(acc[mt][nt], ah[mt], bh0, bh1);
                    MMA_TF32(acc[mt][nt], ah[mt], bl0, bl1);
                    MMA_TF32(acc[mt][nt], al[mt], bh0, bh1);
                }
            }
        }
        __syncthreads();
    }

    // epilogue: bias + relu + scatter by sample id
#pragma unroll
    for (int mt = 0; mt < 2; mt++) {
#pragma unroll
        for (int nt = 0; nt < 8; nt++) {
            int col = n0 + wn * 64 + nt * 8 + tig * 2;
            float bv0 = bias[e * HDIM + col];
            float bv1 = bias[e * HDIM + col + 1];
            int rl0 = wm * 32 + mt * 16 + gid;
            if (rl0 < rows) {
                float v0 = acc[mt][nt][0] + bv0;
                float v1 = acc[mt][nt][1] + bv1;
                if (do_relu) { v0 = fmaxf(v0, 0.f); v1 = fmaxf(v1, 0.f); }
                float* o = out + (size_t)srow[rl0] * HDIM + col;
                o[0] = v0; o[1] = v1;
            }
            int rl1 = rl0 + 8;
            if (rl1 < rows) {
                float v2 = acc[mt][nt][2] + bv0;
                float v3 = acc[mt][nt][3] + bv1;
                if (do_relu) { v2 = fmaxf(v2, 0.f); v3 = fmaxf(v3, 0.f); }
                float* o = out + (size_t)srow[rl1] * HDIM + col;
                o[0] = v2; o[1] = v3;
            }
        }
    }
}

// ---- head: out[b, 0:8] = X[b] @ W3_2[e] + b3_2[e]  (no relu) ---------------
__global__ void head_kernel(int selX,
                            const float* __restrict__ W,    // [NEXP][512][8]
                            const float* __restrict__ bias, // [NEXP][8]
                            float* __restrict__ out)
{
    const float* X = scratch_ptr(selX);
    int warp_global = (blockIdx.x * blockDim.x + threadIdx.x) >> 5;
    int lane = threadIdx.x & 31;
    if (warp_global >= BATCH) return;
    int b = warp_global;
    int e = g_idx[3][b];
    const float* Wr = W + (size_t)e * HDIM * NOUT;
    const float* x  = X + (size_t)b * HDIM;

    float s[NOUT];
#pragma unroll
    for (int o = 0; o < NOUT; o++) s[o] = 0.f;

    for (int k = lane; k < HDIM; k += 32) {
        float xv = x[k];
        const float* wr = Wr + (size_t)k * NOUT;
#pragma unroll
        for (int o = 0; o < NOUT; o++) s[o] += xv * wr[o];
    }
#pragma unroll
    for (int o = 0; o < NOUT; o++) {
#pragma unroll
        for (int d = 16; d > 0; d >>= 1)
            s[o] += __shfl_xor_sync(0xffffffffu, s[o], d);
    }
    if (lane < NOUT) out[(size_t)b * NOUT + lane] = s[lane] + bias[e * NOUT + lane];
}

// ---- launch ---------------------------------------------------------------
extern "C" void kernel_launch(void* const* d_in, const int* in_sizes, int n_in,
                              void* d_out, int out_size)
{
    const float* input = (const float*)d_in[0];
    const float* W00 = (const float*)d_in[1];  const float* b00 = (const float*)d_in[2];
    const float* W01 = (const float*)d_in[3];  const float* b01 = (const float*)d_in[4];
    const float* W10 = (const float*)d_in[5];  const float* b10 = (const float*)d_in[6];
    const float* W11 = (const float*)d_in[7];  const float* b11 = (const float*)d_in[8];
    const float* W20 = (const float*)d_in[9];  const float* b20 = (const float*)d_in[10];
    const float* W21 = (const float*)d_in[11]; const float* b21 = (const float*)d_in[12];
    const float* W30 = (const float*)d_in[13]; const float* b30 = (const float*)d_in[14];
    const float* W31 = (const float*)d_in[15]; const float* b31 = (const float*)d_in[16];
    const float* W32 = (const float*)d_in[17]; const float* b32 = (const float*)d_in[18];

    prep_zero<<<1, 32>>>();
    prep_count<<<BATCH / 256, 256>>>(input);
    prep_scan<<<1, 1>>>();
    prep_scatter<<<BATCH / 256, 256>>>();

    dim3 grid(BATCH / BM, HDIM / BN, NEXP);   // (64, 4, 4)
    // selectors: 0 = g_bufA, 1 = g_bufB, 2 = g_bufH, -1 = external pointer

    // depth 0: feats0 -> A ; A -> B
    gemm_expert<<<grid, NTHREADS>>>(input, -1, INW,  0, 32,   -1,   32, W00, b00, 0, 0, 1);
    gemm_expert<<<grid, NTHREADS>>>(nullptr, 0, HDIM, 0, HDIM, -1, HDIM, W01, b01, 1, 0, 1);
    // depth 1: feats1 -> H ; concat(B, H) -> A
    gemm_expert<<<grid, NTHREADS>>>(input, -1, INW, 32, 32,   -1,   32, W10, b10, 2, 1, 1);
    gemm_expert<<<grid, NTHREADS>>>(nullptr, 1, HDIM, 0, HDIM, 2, 2 * HDIM, W11, b11, 0, 1, 1);
    // depth 2: feats2 -> H ; concat(A, H) -> B
    gemm_expert<<<grid, NTHREADS>>>(input, -1, INW, 64, 32,   -1,   32, W20, b20, 2, 2, 1);
    gemm_expert<<<grid, NTHREADS>>>(nullptr, 0, HDIM, 0, HDIM, 2, 2 * HDIM, W21, b21, 1, 2, 1);
    // depth 3: feats3 -> H ; concat(B, H) -> A
    gemm_expert<<<grid, NTHREADS>>>(input, -1, INW, 96, 32,   -1,   32, W30, b30, 2, 3, 1);
    gemm_expert<<<grid, NTHREADS>>>(nullptr, 1, HDIM, 0, HDIM, 2, 2 * HDIM, W31, b31, 0, 3, 1);
    // head: A -> out
    head_kernel<<<(BATCH * 32 + 255) / 256, 256>>>(0, W32, b32, (float*)d_out);

    (void)in_sizes; (void)n_in; (void)out_size;
}

// round 3
// speedup vs baseline: 1.8123x; 1.8123x over previous
#include <cuda_runtime.h>
#include <cuda_bf16.h>
#include <cstdint>

// ---------------------------------------------------------------------------
// CompositionalMlp: grouped-by-expert GEMM, 3x-bf16-split mma.m16n8k16 + ldmatrix
// ---------------------------------------------------------------------------

#define BATCH  8192
#define NEXP   4
#define NTYPE  4
#define HDIM   512
#define NOUT   8
#define INW    144
#define FEATW  32

#define BM 128
#define BN 128
#define KB 32
#define KBP 40      // padded K stride for A tiles (bf16 elems), 80B rows (16B-aligned)
#define BNP 136     // padded N stride for W tiles (bf16 elems), 272B rows (16B-aligned)
#define NTHREADS 256

// ---- scratch (static device memory; no allocations) -----------------------
__device__ int g_idx[NTYPE][BATCH];
__device__ int g_order[NTYPE][BATCH];
__device__ int g_off[NTYPE][NEXP + 1];
__device__ int g_cnt[NTYPE][NEXP];
__device__ int g_pos[NTYPE][NEXP];

// bf16 hi/lo split weight store (all GEMM weights packed, natural [K,512] layout)
#define OFF_W00 0
#define OFF_W10 65536
#define OFF_W20 131072
#define OFF_W30 196608
#define OFF_W01 262144
#define OFF_W11 1310720
#define OFF_W21 3407872
#define OFF_W31 5505024
#define TOTAL_W 7602176
__device__ __nv_bfloat16 g_Whi[TOTAL_W];
__device__ __nv_bfloat16 g_Wlo[TOTAL_W];
__device__ __nv_bfloat16 g_featHi[BATCH * 128];
__device__ __nv_bfloat16 g_featLo[BATCH * 128];
__device__ __nv_bfloat16 g_actHi[3][BATCH * HDIM];
__device__ __nv_bfloat16 g_actLo[3][BATCH * HDIM];

// ---- helpers ---------------------------------------------------------------
__device__ __forceinline__ uint32_t smem_u32(const void* p) {
    return (uint32_t)__cvta_generic_to_shared(p);
}

#define LDSM_X4(r0, r1, r2, r3, addr)                                         \
    asm volatile("ldmatrix.sync.aligned.m8n8.x4.shared.b16 {%0,%1,%2,%3},[%4];" \
                 : "=r"(r0), "=r"(r1), "=r"(r2), "=r"(r3) : "r"(addr))

#define LDSM_X4T(r0, r1, r2, r3, addr)                                        \
    asm volatile("ldmatrix.sync.aligned.m8n8.x4.trans.shared.b16 {%0,%1,%2,%3},[%4];" \
                 : "=r"(r0), "=r"(r1), "=r"(r2), "=r"(r3) : "r"(addr))

#define MMA_BF16(d, a, b0, b1)                                                \
    asm volatile(                                                             \
        "mma.sync.aligned.m16n8k16.row.col.f32.bf16.bf16.f32 "                \
        "{%0,%1,%2,%3}, {%4,%5,%6,%7}, {%8,%9}, {%0,%1,%2,%3};\n"             \
        : "+f"((d)[0]), "+f"((d)[1]), "+f"((d)[2]), "+f"((d)[3])              \
        : "r"((a)[0]), "r"((a)[1]), "r"((a)[2]), "r"((a)[3]),                 \
          "r"(b0), "r"(b1))

__device__ __forceinline__ void bf16_split(float v, __nv_bfloat16& hi, __nv_bfloat16& lo) {
    hi = __float2bfloat16_rn(v);
    lo = __float2bfloat16_rn(v - __bfloat162float(hi));
}

// ---- prep kernels ----------------------------------------------------------
__global__ void prep_zero() {
    int t = threadIdx.x;
    if (t < NTYPE * NEXP) { ((int*)g_cnt)[t] = 0; ((int*)g_pos)[t] = 0; }
}

__global__ void prep_count(const float* __restrict__ in) {
    int b = blockIdx.x * blockDim.x + threadIdx.x;
    if (b >= BATCH) return;
    const float* oh = in + (size_t)b * INW + 4 * FEATW;
#pragma unroll
    for (int j = 0; j < NTYPE; j++) {
        int e = 0; float best = oh[j * NEXP];
#pragma unroll
        for (int m = 1; m < NEXP; m++) {
            float v = oh[j * NEXP + m];
            if (v > best) { best = v; e = m; }
        }
        g_idx[j][b] = e;
        atomicAdd(&g_cnt[j][e], 1);
    }
}

__global__ void prep_scan() {
    if (threadIdx.x == 0) {
#pragma unroll
        for (int j = 0; j < NTYPE; j++) {
            int s = 0;
#pragma unroll
            for (int e = 0; e < NEXP; e++) { g_off[j][e] = s; s += g_cnt[j][e]; }
            g_off[j][NEXP] = s;
        }
    }
}

__global__ void prep_scatter() {
    int b = blockIdx.x * blockDim.x + threadIdx.x;
    if (b >= BATCH) return;
#pragma unroll
    for (int j = 0; j < NTYPE; j++) {
        int e = g_idx[j][b];
        int p = atomicAdd(&g_pos[j][e], 1);
        g_order[j][g_off[j][e] + p] = b;
    }
}

__global__ void conv_w(const float* __restrict__ src, int n, int dstoff) {
    int i = blockIdx.x * blockDim.x + threadIdx.x;
    if (i >= n) return;
    __nv_bfloat16 hi, lo;
    bf16_split(src[i], hi, lo);
    g_Whi[dstoff + i] = hi;
    g_Wlo[dstoff + i] = lo;
}

__global__ void conv_feats(const float* __restrict__ in) {
    int i = blockIdx.x * blockDim.x + threadIdx.x;
    if (i >= BATCH * 128) return;
    int b = i >> 7, c = i & 127;
    __nv_bfloat16 hi, lo;
    bf16_split(in[(size_t)b * INW + c], hi, lo);
    g_featHi[i] = hi;
    g_featLo[i] = lo;
}

// ---- grouped GEMM ----------------------------------------------------------
// out[rows,512] = relu(A[rows,K] @ W[e] + bias[e]), 3x bf16 split products.
// A gathered per-row: cols [0,K1) from src1 (feats if selA1<0 else act buf),
// cols [K1,K) from act buf selA2. Output -> act buf selOut as bf16 hi/lo.
__global__ __launch_bounds__(NTHREADS)
void gemm_expert(int selA1, int offA1, int K1, int selA2, int K,
                 int wbase, const float* __restrict__ bias,
                 int selOut, int jtype, int do_relu)
{
    __shared__ __nv_bfloat16 Ahi[BM][KBP];
    __shared__ __nv_bfloat16 Alo[BM][KBP];
    __shared__ __nv_bfloat16 Whs[KB][BNP];
    __shared__ __nv_bfloat16 Wls[KB][BNP];
    __shared__ int srow[BM];

    const __nv_bfloat16* A1hi = (selA1 < 0) ? g_featHi : g_actHi[selA1];
    const __nv_bfloat16* A1lo = (selA1 < 0) ? g_featLo : g_actLo[selA1];
    const int lda1 = (selA1 < 0) ? 128 : HDIM;
    const __nv_bfloat16* A2hi = (selA2 < 0) ? nullptr : g_actHi[selA2];
    const __nv_bfloat16* A2lo = (selA2 < 0) ? nullptr : g_actLo[selA2];
    __nv_bfloat16* outHi = g_actHi[selOut];
    __nv_bfloat16* outLo = g_actLo[selOut];

    const int e   = blockIdx.z;
    const int off = g_off[jtype][e];
    const int cnt = g_off[jtype][e + 1] - off;
    const int m0  = blockIdx.x * BM;
    if (m0 >= cnt) return;
    const int rows = min(BM, cnt - m0);
    const int n0   = blockIdx.y * BN;
    const int tid  = threadIdx.x;

    for (int i = tid; i < BM; i += NTHREADS)
        srow[i] = (i < rows) ? g_order[jtype][off + m0 + i] : -1;

    const __nv_bfloat16* Whig = g_Whi + wbase + (size_t)e * K * HDIM;
    const __nv_bfloat16* Wlog = g_Wlo + wbase + (size_t)e * K * HDIM;

    const int warp = tid >> 5, lane = tid & 31;
    const int wm = warp >> 1, wn = warp & 1;   // 4 x 2 warp grid -> 32x64 per warp
    const int gid = lane >> 2, tig = lane & 3;

    // ldmatrix address components
    const int aRow = lane & 15;
    const int aCol = (lane >> 4) << 3;                   // 0 or 8
    const int wRow = (((lane >> 3) & 1) << 3) + (lane & 7);
    const int wCol = (lane >> 4) << 3;                   // 0 or 8

    float acc[2][8][4];
#pragma unroll
    for (int mt = 0; mt < 2; mt++)
#pragma unroll
        for (int nt = 0; nt < 8; nt++)
#pragma unroll
            for (int q = 0; q < 4; q++) acc[mt][nt][q] = 0.f;

    __syncthreads();

    for (int k0 = 0; k0 < K; k0 += KB) {
        // ---- load A tile [BM x KB] (hi & lo), 16B vectors ----
#pragma unroll
        for (int i = 0; i < 2; i++) {
            int flat = i * NTHREADS + tid;
            int r = flat >> 2;          // 4 x uint4 per row
            int q = flat & 3;
            int k = k0 + q * 8;
            int rowid = srow[r];
            uint4 vh = {0, 0, 0, 0}, vl = {0, 0, 0, 0};
            if (rowid >= 0) {
                if (k < K1) {
                    size_t o = (size_t)rowid * lda1 + offA1 + k;
                    vh = *reinterpret_cast<const uint4*>(A1hi + o);
                    vl = *reinterpret_cast<const uint4*>(A1lo + o);
                } else {
                    size_t o = (size_t)rowid * HDIM + (k - K1);
                    vh = *reinterpret_cast<const uint4*>(A2hi + o);
                    vl = *reinterpret_cast<const uint4*>(A2lo + o);
                }
            }
            *reinterpret_cast<uint4*>(&Ahi[r][q * 8]) = vh;
            *reinterpret_cast<uint4*>(&Alo[r][q * 8]) = vl;
        }
        // ---- load W tile [KB x BN] (hi & lo) ----
#pragma unroll
        for (int i = 0; i < 2; i++) {
            int flat = i * NTHREADS + tid;
            int r = flat >> 4;          // 16 x uint4 per row
            int q = flat & 15;
            size_t o = (size_t)(k0 + r) * HDIM + n0 + q * 8;
            *reinterpret_cast<uint4*>(&Whs[r][q * 8]) =
                *reinterpret_cast<const uint4*>(Whig + o);
            *reinterpret_cast<uint4*>(&Wls[r][q * 8]) =
                *reinterpret_cast<const uint4*>(Wlog + o);
        }
        __syncthreads();

#pragma unroll
        for (int ks = 0; ks < KB / 16; ks++) {
            const int kk = ks * 16;
            uint32_t ah[2][4], al[2][4];
#pragma unroll
            for (int mt = 0; mt < 2; mt++) {
                int rb = wm * 32 + mt * 16;
                uint32_t addrH = smem_u32(&Ahi[rb + aRow][kk + aCol]);
                uint32_t addrL = smem_u32(&Alo[rb + aRow][kk + aCol]);
                LDSM_X4(ah[mt][0], ah[mt][1], ah[mt][2], ah[mt][3], addrH);
                LDSM_X4(al[mt][0], al[mt][1], al[mt][2], al[mt][3], addrL);
            }
#pragma unroll
            for (int np = 0; np < 4; np++) {
                int cbase = wn * 64 + np * 16;
                uint32_t bh[4], bl[4];
                uint32_t addrH = smem_u32(&Whs[kk + wRow][cbase + wCol]);
                uint32_t addrL = smem_u32(&Wls[kk + wRow][cbase + wCol]);
                LDSM_X4T(bh[0], bh[1], bh[2], bh[3], addrH);
                LDSM_X4T(bl[0], bl[1], bl[2], bl[3], addrL);
#pragma unroll
                for (int mt = 0; mt < 2; mt++) {
                    MMA_BF16(acc[mt][2 * np],     ah[mt], bh[0], bh[1]);
                    MMA_BF16(acc[mt][2 * np],     ah[mt], bl[0], bl[1]);
                    MMA_BF16(acc[mt][2 * np],     al[mt], bh[0], bh[1]);
                    MMA_BF16(acc[mt][2 * np + 1], ah[mt], bh[2], bh[3]);
                    MMA_BF16(acc[mt][2 * np + 1], ah[mt], bl[2], bl[3]);
                    MMA_BF16(acc[mt][2 * np + 1], al[mt], bh[2], bh[3]);
                }
            }
        }
        __syncthreads();
    }

    // ---- epilogue: bias + relu + bf16-split scatter ----
#pragma unroll
    for (int mt = 0; mt < 2; mt++) {
#pragma unroll
        for (int nt = 0; nt < 8; nt++) {
            int col = n0 + wn * 64 + nt * 8 + tig * 2;
            float bv0 = bias[e * HDIM + col];
            float bv1 = bias[e * HDIM + col + 1];
            int rl0 = wm * 32 + mt * 16 + gid;
            if (rl0 < rows) {
                float v0 = acc[mt][nt][0] + bv0;
                float v1 = acc[mt][nt][1] + bv1;
                if (do_relu) { v0 = fmaxf(v0, 0.f); v1 = fmaxf(v1, 0.f); }
                __nv_bfloat16 h0, l0, h1, l1;
                bf16_split(v0, h0, l0); bf16_split(v1, h1, l1);
                size_t o = (size_t)srow[rl0] * HDIM + col;
                *reinterpret_cast<__nv_bfloat162*>(outHi + o) = __nv_bfloat162(h0, h1);
                *reinterpret_cast<__nv_bfloat162*>(outLo + o) = __nv_bfloat162(l0, l1);
            }
            int rl1 = rl0 + 8;
            if (rl1 < rows) {
                float v2 = acc[mt][nt][2] + bv0;
                float v3 = acc[mt][nt][3] + bv1;
                if (do_relu) { v2 = fmaxf(v2, 0.f); v3 = fmaxf(v3, 0.f); }
                __nv_bfloat16 h2, l2, h3, l3;
                bf16_split(v2, h2, l2); bf16_split(v3, h3, l3);
                size_t o = (size_t)srow[rl1] * HDIM + col;
                *reinterpret_cast<__nv_bfloat162*>(outHi + o) = __nv_bfloat162(h2, h3);
                *reinterpret_cast<__nv_bfloat162*>(outLo + o) = __nv_bfloat162(l2, l3);
            }
        }
    }
}

// ---- head: out[b,0:8] = X[b] @ W3_2[e] + b3_2[e] ---------------------------
__global__ void head_kernel(const float* __restrict__ W,    // [NEXP][512][8]
                            const float* __restrict__ bias, // [NEXP][8]
                            float* __restrict__ out)
{
    int warp_global = (blockIdx.x * blockDim.x + threadIdx.x) >> 5;
    int lane = threadIdx.x & 31;
    if (warp_global >= BATCH) return;
    int b = warp_global;
    int e = g_idx[3][b];
    const float* Wr = W + (size_t)e * HDIM * NOUT;
    const __nv_bfloat16* xh = g_actHi[0] + (size_t)b * HDIM;
    const __nv_bfloat16* xl = g_actLo[0] + (size_t)b * HDIM;

    float s[NOUT];
#pragma unroll
    for (int o = 0; o < NOUT; o++) s[o] = 0.f;

    for (int k = lane; k < HDIM; k += 32) {
        float xv = __bfloat162float(xh[k]) + __bfloat162float(xl[k]);
        const float* wr = Wr + (size_t)k * NOUT;
#pragma unroll
        for (int o = 0; o < NOUT; o++) s[o] += xv * wr[o];
    }
#pragma unroll
    for (int o = 0; o < NOUT; o++) {
#pragma unroll
        for (int d = 16; d > 0; d >>= 1)
            s[o] += __shfl_xor_sync(0xffffffffu, s[o], d);
    }
    if (lane < NOUT) out[(size_t)b * NOUT + lane] = s[lane] + bias[e * NOUT + lane];
}

// ---- launch ---------------------------------------------------------------
extern "C" void kernel_launch(void* const* d_in, const int* in_sizes, int n_in,
                              void* d_out, int out_size)
{
    const float* input = (const float*)d_in[0];
    const float* W00 = (const float*)d_in[1];  const float* b00 = (const float*)d_in[2];
    const float* W01 = (const float*)d_in[3];  const float* b01 = (const float*)d_in[4];
    const float* W10 = (const float*)d_in[5];  const float* b10 = (const float*)d_in[6];
    const float* W11 = (const float*)d_in[7];  const float* b11 = (const float*)d_in[8];
    const float* W20 = (const float*)d_in[9];  const float* b20 = (const float*)d_in[10];
    const float* W21 = (const float*)d_in[11]; const float* b21 = (const float*)d_in[12];
    const float* W30 = (const float*)d_in[13]; const float* b30 = (const float*)d_in[14];
    const float* W31 = (const float*)d_in[15]; const float* b31 = (const float*)d_in[16];
    const float* W32 = (const float*)d_in[17]; const float* b32 = (const float*)d_in[18];

    prep_zero<<<1, 32>>>();
    prep_count<<<BATCH / 256, 256>>>(input);
    prep_scan<<<1, 1>>>();
    prep_scatter<<<BATCH / 256, 256>>>();

    conv_feats<<<(BATCH * 128) / 256, 256>>>(input);
    conv_w<<<(65536 + 255) / 256, 256>>>(W00, 65536, OFF_W00);
    conv_w<<<(65536 + 255) / 256, 256>>>(W10, 65536, OFF_W10);
    conv_w<<<(65536 + 255) / 256, 256>>>(W20, 65536, OFF_W20);
    conv_w<<<(65536 + 255) / 256, 256>>>(W30, 65536, OFF_W30);
    conv_w<<<(1048576 + 255) / 256, 256>>>(W01, 1048576, OFF_W01);
    conv_w<<<(2097152 + 255) / 256, 256>>>(W11, 2097152, OFF_W11);
    conv_w<<<(2097152 + 255) / 256, 256>>>(W21, 2097152, OFF_W21);
    conv_w<<<(2097152 + 255) / 256, 256>>>(W31, 2097152, OFF_W31);

    dim3 grid(BATCH / BM, HDIM / BN, NEXP);   // (64, 4, 4)

    // depth 0: feats0 -> act0 ; act0 -> act1
    gemm_expert<<<grid, NTHREADS>>>(-1,  0,  32, -1,   32, OFF_W00, b00, 0, 0, 1);
    gemm_expert<<<grid, NTHREADS>>>( 0,  0, 512, -1,  512, OFF_W01, b01, 1, 0, 1);
    // depth 1: feats1 -> act2 ; concat(act1, act2) -> act0
    gemm_expert<<<grid, NTHREADS>>>(-1, 32,  32, -1,   32, OFF_W10, b10, 2, 1, 1);
    gemm_expert<<<grid, NTHREADS>>>( 1,  0, 512,  2, 1024, OFF_W11, b11, 0, 1, 1);
    // depth 2: feats2 -> act2 ; concat(act0, act2) -> act1
    gemm_expert<<<grid, NTHREADS>>>(-1, 64,  32, -1,   32, OFF_W20, b20, 2, 2, 1);
    gemm_expert<<<grid, NTHREADS>>>( 0,  0, 512,  2, 1024, OFF_W21, b21, 1, 2, 1);
    // depth 3: feats3 -> act2 ; concat(act1, act2) -> act0
    gemm_expert<<<grid, NTHREADS>>>(-1, 96,  32, -1,   32, OFF_W30, b30, 2, 3, 1);
    gemm_expert<<<grid, NTHREADS>>>( 1,  0, 512,  2, 1024, OFF_W31, b31, 0, 3, 1);
    // head: act0 -> out
    head_kernel<<<(BATCH * 32 + 255) / 256, 256>>>(W32, b32, (float*)d_out);

    (void)in_sizes; (void)n_in; (void)out_size;
}

// round 5
// speedup vs baseline: 1.8255x; 1.0073x over previous
#include <cuda_runtime.h>
#include <cstdint>

// ---------------------------------------------------------------------------
// CompositionalMlp: grouped-by-expert GEMM, int8 dual-word (15-bit) emulation
// via mma.sync.m16n8k32.s8.s32 + ldmatrix + cp.async 3-stage pipeline.
// (tcgen05 unavailable: harness compiles at baseline .target sm_100)
// ---------------------------------------------------------------------------

#define BATCH  8192
#define NEXP   4
#define NTYPE  4
#define HDIM   512
#define NOUT   8
#define INW    144

#define BM 128
#define BN 64
#define KB 64
#define ROWB 80                 // smem bytes per tile row (64 data + 16 pad)
#define SLOT 30720              // A1(10240)+A0(10240)+B1(5120)+B0(5120)
#define SMEM_TOT (512 + 3 * SLOT)

// ---- scratch ----------------------------------------------------------------
__device__ int g_idx[NTYPE][BATCH];
__device__ int g_order[NTYPE][BATCH];
__device__ int g_off[NTYPE][NEXP + 1];
__device__ int g_cnt[NTYPE][NEXP];
__device__ int g_pos[NTYPE][NEXP];

// quantized weights [e][N=512][K] (transposed), dual int8 words
#define OFF_W00 0
#define OFF_W10 65536
#define OFF_W20 131072
#define OFF_W30 196608
#define OFF_W01 262144
#define OFF_W11 1310720
#define OFF_W21 3407872
#define OFF_W31 5505024
#define TOTAL_W 7602176
__device__ int8_t  g_wq1[TOTAL_W];
__device__ int8_t  g_wq0[TOTAL_W];
__device__ float   g_sW[8 * 2048];
__device__ float   g_sWinv[8 * 2048];
__device__ unsigned g_sWmaxU[8 * 2048];

__device__ int8_t  g_qf1[BATCH * 128];
__device__ int8_t  g_qf0[BATCH * 128];
__device__ float   g_sfeat[4 * BATCH];
__device__ int8_t  g_qa1[BATCH * 1024];
__device__ int8_t  g_qa0[BATCH * 1024];
__device__ float   g_sact[BATCH];
__device__ unsigned g_rowmax[8][BATCH];

__device__ float g_actA[BATCH * HDIM];
__device__ float g_actB[BATCH * HDIM];
__device__ float g_actH[BATCH * HDIM];

__device__ __forceinline__ float* act_ptr(int sel) {
    return sel == 0 ? g_actA : (sel == 1 ? g_actB : g_actH);
}

// ---- PTX helpers ------------------------------------------------------------
__device__ __forceinline__ uint32_t smem_u32(const void* p) {
    return (uint32_t)__cvta_generic_to_shared(p);
}

#define CP_ASYNC16(dst, src, sz) \
    asm volatile("cp.async.cg.shared.global [%0], [%1], 16, %2;" \
                 :: "r"(dst), "l"(src), "r"(sz) : "memory")
#define CP_COMMIT() asm volatile("cp.async.commit_group;" ::: "memory")

#define LDSM4(r, addr)                                                        \
    asm volatile("ldmatrix.sync.aligned.m8n8.x4.shared.b16 {%0,%1,%2,%3},[%4];" \
                 : "=r"((r)[0]), "=r"((r)[1]), "=r"((r)[2]), "=r"((r)[3])     \
                 : "r"(addr))

#define MMA_S8(d, a, b0, b1)                                                  \
    asm volatile("mma.sync.aligned.m16n8k32.row.col.s32.s8.s8.s32 "           \
                 "{%0,%1,%2,%3},{%4,%5,%6,%7},{%8,%9},{%0,%1,%2,%3};"         \
                 : "+r"((d)[0]), "+r"((d)[1]), "+r"((d)[2]), "+r"((d)[3])     \
                 : "r"((a)[0]), "r"((a)[1]), "r"((a)[2]), "r"((a)[3]),        \
                   "r"(b0), "r"(b1))

__device__ __forceinline__ void quant_pair(float x, int8_t& q1, int8_t& q0) {
    float h = rintf(x * (1.f / 128.f));
    h = fminf(fmaxf(h, -127.f), 127.f);
    float l = rintf(x - 128.f * h);
    l = fminf(fmaxf(l, -127.f), 127.f);
    q1 = (int8_t)(int)h;
    q0 = (int8_t)(int)l;
}

// ---- prep kernels -----------------------------------------------------------
__global__ void prep_zero() {
    int t = threadIdx.x;
    if (t < NTYPE * NEXP) { ((int*)g_cnt)[t] = 0; ((int*)g_pos)[t] = 0; }
}

__global__ void prep_reset() {
    int i = blockIdx.x * 256 + threadIdx.x;
    if (i < 8 * BATCH) ((unsigned*)g_rowmax)[i] = 0;
    if (i < 8 * 2048)  g_sWmaxU[i] = 0;
}

__global__ void prep_count(const float* __restrict__ in) {
    int b = blockIdx.x * blockDim.x + threadIdx.x;
    if (b >= BATCH) return;
    const float* oh = in + (size_t)b * INW + 128;
#pragma unroll
    for (int j = 0; j < NTYPE; j++) {
        int e = 0; float best = oh[j * NEXP];
#pragma unroll
        for (int m = 1; m < NEXP; m++) {
            float v = oh[j * NEXP + m];
            if (v > best) { best = v; e = m; }
        }
        g_idx[j][b] = e;
        atomicAdd(&g_cnt[j][e], 1);
    }
}

__global__ void prep_scan() {
    if (threadIdx.x == 0) {
#pragma unroll
        for (int j = 0; j < NTYPE; j++) {
            int s = 0;
#pragma unroll
            for (int e = 0; e < NEXP; e++) { g_off[j][e] = s; s += g_cnt[j][e]; }
            g_off[j][NEXP] = s;
        }
    }
}

__global__ void prep_scatter() {
    int b = blockIdx.x * blockDim.x + threadIdx.x;
    if (b >= BATCH) return;
#pragma unroll
    for (int j = 0; j < NTYPE; j++) {
        int e = g_idx[j][b];
        int p = atomicAdd(&g_pos[j][e], 1);
        g_order[j][g_off[j][e] + p] = b;
    }
}

// ---- weight quantization ----------------------------------------------------
__global__ void wabs(const float* __restrict__ src, int K, int swoff) {
    int numc = (K + 127) / 128;
    int idx = blockIdx.x * 256 + threadIdx.x;
    if (idx >= 2048 * numc) return;
    int c = idx / 2048, en = idx % 2048;
    int e = en >> 9, n = en & 511;
    const float* s = src + (size_t)e * K * 512 + n;
    int k0 = c * 128, k1 = min(K, k0 + 128);
    float m = 0.f;
    for (int k = k0; k < k1; k++) m = fmaxf(m, fabsf(s[(size_t)k * 512]));
    atomicMax(&g_sWmaxU[swoff + en], __float_as_uint(m));
}

__global__ void sfinal() {
    int i = blockIdx.x * 256 + threadIdx.x;
    if (i >= 8 * 2048) return;
    float m = __uint_as_float(g_sWmaxU[i]);
    g_sW[i] = m / 16256.f;
    g_sWinv[i] = (m > 0.f) ? 16256.f / m : 0.f;
}

// transpose + quantize: src [e][K][512] fp32 -> [e][512][K] int8 pairs
__global__ void wquant(const float* __restrict__ src, int K, int qoff, int swoff) {
    __shared__ float t[32][33];
    int e = blockIdx.z;
    int k0 = blockIdx.x * 32, n0 = blockIdx.y * 32;
    const float* s = src + (size_t)e * K * 512;
#pragma unroll
    for (int i = 0; i < 4; i++) {
        int kr = threadIdx.y + i * 8;
        t[kr][threadIdx.x] = s[(size_t)(k0 + kr) * 512 + n0 + threadIdx.x];
    }
    __syncthreads();
#pragma unroll
    for (int i = 0; i < 4; i++) {
        int n = n0 + threadIdx.y + i * 8;
        float inv = g_sWinv[swoff + e * 512 + n];
        float x = t[threadIdx.x][threadIdx.y + i * 8] * inv;
        int8_t q1, q0; quant_pair(x, q1, q0);
        size_t o = (size_t)qoff + (size_t)(e * 512 + n) * K + k0 + threadIdx.x;
        g_wq1[o] = q1;
        g_wq0[o] = q0;
    }
}

// ---- activation / feature quantization -------------------------------------
__global__ void quant_feats(const float* __restrict__ in) {
    int w = (blockIdx.x * blockDim.x + threadIdx.x) >> 5;
    int lane = threadIdx.x & 31;
    if (w >= BATCH * 4) return;
    int b = w >> 2, j = w & 3;
    float v = in[(size_t)b * INW + j * 32 + lane];
    float a = fabsf(v);
#pragma unroll
    for (int d = 16; d; d >>= 1) a = fmaxf(a, __shfl_xor_sync(0xffffffffu, a, d));
    float inv = (a > 0.f) ? 16256.f / a : 0.f;
    int8_t q1, q0; quant_pair(v * inv, q1, q0);
    g_qf1[b * 128 + j * 32 + lane] = q1;
    g_qf0[b * 128 + j * 32 + lane] = q0;
    if (lane == 0) g_sfeat[j * BATCH + b] = a / 16256.f;
}

// quantize activations; selH >= 0 -> concat [X | H] with joint per-row scale
__global__ void quant_act(int selX, int selH, int slotX, int slotH, int Ktot) {
    int i = blockIdx.x * 256 + threadIdx.x;
    if (i >= BATCH * Ktot) return;
    int b = i / Ktot, c = i % Ktot;
    float rmx = __uint_as_float(g_rowmax[slotX][b]);
    if (selH >= 0) rmx = fmaxf(rmx, __uint_as_float(g_rowmax[slotH][b]));
    float v = (c < 512) ? act_ptr(selX)[(size_t)b * 512 + c]
                        : act_ptr(selH)[(size_t)b * 512 + (c - 512)];
    float inv = (rmx > 0.f) ? 16256.f / rmx : 0.f;
    int8_t q1, q0; quant_pair(v * inv, q1, q0);
    g_qa1[(size_t)b * Ktot + c] = q1;
    g_qa0[(size_t)b * Ktot + c] = q0;
    if (c == 0) g_sact[b] = rmx / 16256.f;
}

// ---- int8 grouped GEMM ------------------------------------------------------
__global__ __launch_bounds__(256, 2)
void gemm_i8(int aSel, int lda, int offA, int K, int sAoff,
             int woff, int swoff, const float* __restrict__ bias,
             int outSel, int rmslot, int jtype)
{
    extern __shared__ char sm[];
    int* srow = (int*)sm;
    char* tiles = sm + 512;

    const int e   = blockIdx.z;
    const int off = g_off[jtype][e];
    const int cnt = g_off[jtype][e + 1] - off;
    const int m0  = blockIdx.x * BM;
    if (m0 >= cnt) return;
    const int rows = min(BM, cnt - m0);
    const int n0   = blockIdx.y * BN;
    const int tid  = threadIdx.x;
    const int wid  = tid >> 5, lane = tid & 31;
    const int wm   = wid >> 1, wn = wid & 1;

    const int8_t* Aq1 = aSel ? g_qa1 : g_qf1;
    const int8_t* Aq0 = aSel ? g_qa0 : g_qf0;
    const float*  sA  = (aSel ? g_sact : g_sfeat) + sAoff;
    float* outF = act_ptr(outSel);
    unsigned* rowmax = g_rowmax[rmslot];

    for (int i = tid; i < BM; i += 256)
        srow[i] = (i < rows) ? g_order[jtype][off + m0 + i] : -1;
    __syncthreads();

    const int8_t* Wq1 = g_wq1 + woff + (size_t)(e * 512 + n0) * K;
    const int8_t* Wq0 = g_wq0 + woff + (size_t)(e * 512 + n0) * K;

    const int nchunk = (K + KB - 1) / KB;

    auto issue = [&](int c) {
        char* base = tiles + (c % 3) * SLOT;
        int k0 = c * KB;
#pragma unroll
        for (int i = 0; i < 4; i++) {            // A: 128 rows x 64B x 2 tensors
            int flat = i * 256 + tid;
            int tensor = flat >> 9, rem = flat & 511;
            int r = rem >> 2, seg = rem & 3;
            int rowid = srow[r];
            int k = k0 + seg * 16;
            const int8_t* src = tensor ? Aq0 : Aq1;
            const int8_t* gp = src + ((size_t)(rowid < 0 ? 0 : rowid) * lda + offA + k);
            uint32_t dst = smem_u32(base + tensor * 10240 + r * ROWB + seg * 16);
            int sz = (rowid >= 0 && k + 16 <= K) ? 16 : 0;
            CP_ASYNC16(dst, gp, sz);
        }
#pragma unroll
        for (int i = 0; i < 2; i++) {            // B: 64 rows x 64B x 2 tensors
            int flat = i * 256 + tid;
            int tensor = flat >> 8, rem = flat & 255;
            int r = rem >> 2, seg = rem & 3;
            int k = k0 + seg * 16;
            const int8_t* src = tensor ? Wq0 : Wq1;
            const int8_t* gp = src + ((size_t)r * K + k);
            uint32_t dst = smem_u32(base + 20480 + tensor * 5120 + r * ROWB + seg * 16);
            int sz = (k + 16 <= K) ? 16 : 0;
            CP_ASYNC16(dst, gp, sz);
        }
        CP_COMMIT();
    };

    int acc1[2][4][4], acc2[2][4][4];
#pragma unroll
    for (int mt = 0; mt < 2; mt++)
#pragma unroll
        for (int j = 0; j < 4; j++)
#pragma unroll
            for (int q = 0; q < 4; q++) { acc1[mt][j][q] = 0; acc2[mt][j][q] = 0; }

    issue(0);
    if (nchunk > 1) issue(1);

    // ldmatrix lane addressing
    const int aRow  = lane & 15;
    const int aHalf = lane >> 4;
    const int bRow  = ((lane >> 4) << 3) + (lane & 7);
    const int bHalf = (lane >> 3) & 1;

    for (int c = 0; c < nchunk; c++) {
        if (c + 1 < nchunk) asm volatile("cp.async.wait_group 1;" ::: "memory");
        else                asm volatile("cp.async.wait_group 0;" ::: "memory");
        __syncthreads();
        if (c + 2 < nchunk) issue(c + 2);

        char* base = tiles + (c % 3) * SLOT;
#pragma unroll
        for (int s = 0; s < 2; s++) {            // two k32 steps per chunk
            uint32_t a1[2][4], a0[2][4];
#pragma unroll
            for (int mt = 0; mt < 2; mt++) {
                uint32_t ra = smem_u32(base + (wm * 32 + mt * 16 + aRow) * ROWB
                                       + s * 32 + aHalf * 16);
                LDSM4(a1[mt], ra);
                LDSM4(a0[mt], ra + 10240);
            }
#pragma unroll
            for (int ng = 0; ng < 2; ng++) {
                int nrow = wn * 32 + ng * 16 + bRow;
                uint32_t rb = smem_u32(base + 20480 + nrow * ROWB
                                       + s * 32 + bHalf * 16);
                uint32_t b1[4], b0[4];
                LDSM4(b1, rb);
                LDSM4(b0, rb + 5120);
#pragma unroll
                for (int jt = 0; jt < 2; jt++) {
                    int j = ng * 2 + jt;
#pragma unroll
                    for (int mt = 0; mt < 2; mt++) {
                        MMA_S8(acc1[mt][j], a1[mt], b1[2 * jt], b1[2 * jt + 1]);
                        MMA_S8(acc2[mt][j], a1[mt], b0[2 * jt], b0[2 * jt + 1]);
                        MMA_S8(acc2[mt][j], a0[mt], b1[2 * jt], b1[2 * jt + 1]);
                    }
                }
            }
        }
    }

    // ---- epilogue: scale combine + bias + relu + scatter + rowmax ----------
    const float* sWl = g_sW + swoff + e * 512 + n0;
    const float* bl  = bias + e * 512 + n0;
    const int gid = lane >> 2, tig = lane & 3;
#pragma unroll
    for (int mt = 0; mt < 2; mt++) {
#pragma unroll
        for (int h = 0; h < 2; h++) {
            int rl = wm * 32 + mt * 16 + gid + h * 8;
            if (rl >= rows) continue;
            int gr = srow[rl];
            float sa = sA[gr];
            float rmx = 0.f;
#pragma unroll
            for (int j = 0; j < 4; j++) {
                int col = wn * 32 + j * 8 + tig * 2;
                int i0 = h * 2;
                float c0 = (float)acc1[mt][j][i0] * 16384.f
                         + (float)acc2[mt][j][i0] * 128.f;
                float c1 = (float)acc1[mt][j][i0 + 1] * 16384.f
                         + (float)acc2[mt][j][i0 + 1] * 128.f;
                float v0 = fmaxf(sa * sWl[col] * c0 + bl[col], 0.f);
                float v1 = fmaxf(sa * sWl[col + 1] * c1 + bl[col + 1], 0.f);
                rmx = fmaxf(rmx, fmaxf(v0, v1));
                float2 f2; f2.x = v0; f2.y = v1;
                *(float2*)(outF + (size_t)gr * 512 + n0 + col) = f2;
            }
            atomicMax(rowmax + gr, __float_as_uint(rmx));
        }
    }
}

// ---- head: out[b,0:8] = X[b] @ W3_2[e] + b3_2[e]  (no relu) ----------------
__global__ void head_kernel(const float* __restrict__ W,
                            const float* __restrict__ bias,
                            float* __restrict__ out)
{
    int warp_global = (blockIdx.x * blockDim.x + threadIdx.x) >> 5;
    int lane = threadIdx.x & 31;
    if (warp_global >= BATCH) return;
    int b = warp_global;
    int e = g_idx[3][b];
    const float* Wr = W + (size_t)e * HDIM * NOUT;
    const float* x  = g_actA + (size_t)b * HDIM;

    float s[NOUT];
#pragma unroll
    for (int o = 0; o < NOUT; o++) s[o] = 0.f;
    for (int k = lane; k < HDIM; k += 32) {
        float xv = x[k];
        const float* wr = Wr + (size_t)k * NOUT;
#pragma unroll
        for (int o = 0; o < NOUT; o++) s[o] += xv * wr[o];
    }
#pragma unroll
    for (int o = 0; o < NOUT; o++) {
#pragma unroll
        for (int d = 16; d > 0; d >>= 1)
            s[o] += __shfl_xor_sync(0xffffffffu, s[o], d);
    }
    if (lane < NOUT) out[(size_t)b * NOUT + lane] = s[lane] + bias[e * NOUT + lane];
}

// ---- launch -----------------------------------------------------------------
extern "C" void kernel_launch(void* const* d_in, const int* in_sizes, int n_in,
                              void* d_out, int out_size)
{
    const float* input = (const float*)d_in[0];
    const float* W00 = (const float*)d_in[1];  const float* b00 = (const float*)d_in[2];
    const float* W01 = (const float*)d_in[3];  const float* b01 = (const float*)d_in[4];
    const float* W10 = (const float*)d_in[5];  const float* b10 = (const float*)d_in[6];
    const float* W11 = (const float*)d_in[7];  const float* b11 = (const float*)d_in[8];
    const float* W20 = (const float*)d_in[9];  const float* b20 = (const float*)d_in[10];
    const float* W21 = (const float*)d_in[11]; const float* b21 = (const float*)d_in[12];
    const float* W30 = (const float*)d_in[13]; const float* b30 = (const float*)d_in[14];
    const float* W31 = (const float*)d_in[15]; const float* b31 = (const float*)d_in[16];
    const float* W32 = (const float*)d_in[17]; const float* b32 = (const float*)d_in[18];

    static int smem_set = 0;
    if (!smem_set) {
        cudaFuncSetAttribute(gemm_i8, cudaFuncAttributeMaxDynamicSharedMemorySize, SMEM_TOT);
        smem_set = 1;
    }

    prep_zero<<<1, 32>>>();
    prep_reset<<<(8 * BATCH + 255) / 256, 256>>>();
    prep_count<<<BATCH / 256, 256>>>(input);
    prep_scan<<<1, 1>>>();
    prep_scatter<<<BATCH / 256, 256>>>();

    quant_feats<<<(BATCH * 4 * 32 + 255) / 256, 256>>>(input);

    wabs<<<(2048 + 255) / 256, 256>>>(W00, 32, 0 * 2048);
    wabs<<<(2048 + 255) / 256, 256>>>(W10, 32, 1 * 2048);
    wabs<<<(2048 + 255) / 256, 256>>>(W20, 32, 2 * 2048);
    wabs<<<(2048 + 255) / 256, 256>>>(W30, 32, 3 * 2048);
    wabs<<<(2048 * 4 + 255) / 256, 256>>>(W01, 512, 4 * 2048);
    wabs<<<(2048 * 8 + 255) / 256, 256>>>(W11, 1024, 5 * 2048);
    wabs<<<(2048 * 8 + 255) / 256, 256>>>(W21, 1024, 6 * 2048);
    wabs<<<(2048 * 8 + 255) / 256, 256>>>(W31, 1024, 7 * 2048);
    sfinal<<<(8 * 2048 + 255) / 256, 256>>>();

    dim3 tb(32, 8);
    wquant<<<dim3(1, 16, 4),  tb>>>(W00,   32, OFF_W00, 0 * 2048);
    wquant<<<dim3(1, 16, 4),  tb>>>(W10,   32, OFF_W10, 1 * 2048);
    wquant<<<dim3(1, 16, 4),  tb>>>(W20,   32, OFF_W20, 2 * 2048);
    wquant<<<dim3(1, 16, 4),  tb>>>(W30,   32, OFF_W30, 3 * 2048);
    wquant<<<dim3(16, 16, 4), tb>>>(W01,  512, OFF_W01, 4 * 2048);
    wquant<<<dim3(32, 16, 4), tb>>>(W11, 1024, OFF_W11, 5 * 2048);
    wquant<<<dim3(32, 16, 4), tb>>>(W21, 1024, OFF_W21, 6 * 2048);
    wquant<<<dim3(32, 16, 4), tb>>>(W31, 1024, OFF_W31, 7 * 2048);

    dim3 grid(BATCH / BM, HDIM / BN, NEXP);   // (64, 8, 4)
#define GEMM(aSel, lda, offA, K, sAoff, woff, swoff, bias, outSel, rms, jt) \
    gemm_i8<<<grid, 256, SMEM_TOT>>>(aSel, lda, offA, K, sAoff, woff, swoff, bias, outSel, rms, jt)

    // L00: feats0 -> A (slot0)
    GEMM(0, 128,  0,   32, 0 * BATCH, OFF_W00, 0 * 2048, b00, 0, 0, 0);
    quant_act<<<(BATCH * 512 + 255) / 256, 256>>>(0, -1, 0, 0, 512);
    // L01: qa -> B (slot4)
    GEMM(1, 512,  0,  512, 0,         OFF_W01, 4 * 2048, b01, 1, 4, 0);
    // L10: feats1 -> H (slot1)
    GEMM(0, 128, 32,   32, 1 * BATCH, OFF_W10, 1 * 2048, b10, 2, 1, 1);
    quant_act<<<(BATCH * 1024 + 255) / 256, 256>>>(1, 2, 4, 1, 1024);
    // L11: qa -> A (slot5)
    GEMM(1, 1024, 0, 1024, 0,         OFF_W11, 5 * 2048, b11, 0, 5, 1);
    // L20: feats2 -> H (slot2)
    GEMM(0, 128, 64,   32, 2 * BATCH, OFF_W20, 2 * 2048, b20, 2, 2, 2);
    quant_act<<<(BATCH * 1024 + 255) / 256, 256>>>(0, 2, 5, 2, 1024);
    // L21: qa -> B (slot6)
    GEMM(1, 1024, 0, 1024, 0,         OFF_W21, 6 * 2048, b21, 1, 6, 2);
    // L30: feats3 -> H (slot3)
    GEMM(0, 128, 96,   32, 3 * BATCH, OFF_W30, 3 * 2048, b30, 2, 3, 3);
    quant_act<<<(BATCH * 1024 + 255) / 256, 256>>>(1, 2, 6, 3, 1024);
    // L31: qa -> A (slot7)
    GEMM(1, 1024, 0, 1024, 0,         OFF_W31, 7 * 2048, b31, 0, 7, 3);
    // head
    head_kernel<<<(BATCH * 32 + 255) / 256, 256>>>(W32, b32, (float*)d_out);

    (void)in_sizes; (void)n_in; (void)out_size;
}

// round 7
// speedup vs baseline: 2.0310x; 1.1126x over previous
#include <cuda_runtime.h>
#include <cstdint>

// ---------------------------------------------------------------------------
// CompositionalMlp: grouped-by-expert GEMM, int8 dual-word (15-bit) emulation
// via mma.sync.m16n8k32.s8.s32 + ldmatrix + cp.async 3-stage pipeline.
// R7: R6 + aligned shared tiles in wprep, no static guards.
// ---------------------------------------------------------------------------

#define BATCH  8192
#define NEXP   4
#define NTYPE  4
#define HDIM   512
#define NOUT   8
#define INW    144

#define BM 128
#define BN 64
#define KB 64
#define ROWB 80                 // smem bytes per tile row (64 data + 16 pad)
#define SLOT 30720              // A1(10240)+A0(10240)+B1(5120)+B0(5120)
#define SMEM_TOT (512 + 3 * SLOT)

// ---- scratch ----------------------------------------------------------------
__device__ int g_idx[NTYPE][BATCH];
__device__ int g_order[NTYPE][BATCH];
__device__ int g_off[NTYPE][NEXP + 1];

// quantized weights [e][N=512][K] (transposed), dual int8 words
#define OFF_W00 0
#define OFF_W10 65536
#define OFF_W20 131072
#define OFF_W30 196608
#define OFF_W01 262144
#define OFF_W11 1310720
#define OFF_W21 3407872
#define OFF_W31 5505024
#define TOTAL_W 7602176
__device__ __align__(16) int8_t  g_wq1[TOTAL_W];
__device__ __align__(16) int8_t  g_wq0[TOTAL_W];
__device__ float   g_sW[8 * 2048];

__device__ __align__(16) int8_t  g_qf1[BATCH * 128];
__device__ __align__(16) int8_t  g_qf0[BATCH * 128];
__device__ float   g_sfeat[4 * BATCH];
__device__ __align__(16) int8_t  g_qa1[BATCH * 1024];
__device__ __align__(16) int8_t  g_qa0[BATCH * 1024];
__device__ float   g_sact[BATCH];
__device__ unsigned g_rowmax[8][BATCH];

__device__ float g_actA[BATCH * HDIM];
__device__ float g_actB[BATCH * HDIM];
__device__ float g_actH[BATCH * HDIM];

__device__ __forceinline__ float* act_ptr(int sel) {
    return sel == 0 ? g_actA : (sel == 1 ? g_actB : g_actH);
}

// ---- PTX helpers ------------------------------------------------------------
__device__ __forceinline__ uint32_t smem_u32(const void* p) {
    return (uint32_t)__cvta_generic_to_shared(p);
}

#define CP_ASYNC16(dst, src, sz) \
    asm volatile("cp.async.cg.shared.global [%0], [%1], 16, %2;" \
                 :: "r"(dst), "l"(src), "r"(sz) : "memory")
#define CP_COMMIT() asm volatile("cp.async.commit_group;" ::: "memory")

#define LDSM4(r, addr)                                                        \
    asm volatile("ldmatrix.sync.aligned.m8n8.x4.shared.b16 {%0,%1,%2,%3},[%4];" \
                 : "=r"((r)[0]), "=r"((r)[1]), "=r"((r)[2]), "=r"((r)[3])     \
                 : "r"(addr))

#define MMA_S8(d, a, b0, b1)                                                  \
    asm volatile("mma.sync.aligned.m16n8k32.row.col.s32.s8.s8.s32 "           \
                 "{%0,%1,%2,%3},{%4,%5,%6,%7},{%8,%9},{%0,%1,%2,%3};"         \
                 : "+r"((d)[0]), "+r"((d)[1]), "+r"((d)[2]), "+r"((d)[3])     \
                 : "r"((a)[0]), "r"((a)[1]), "r"((a)[2]), "r"((a)[3]),        \
                   "r"(b0), "r"(b1))

__device__ __forceinline__ void quant_pair(float x, int8_t& q1, int8_t& q0) {
    float h = rintf(x * (1.f / 128.f));
    h = fminf(fmaxf(h, -127.f), 127.f);
    float l = rintf(x - 128.f * h);
    l = fminf(fmaxf(l, -127.f), 127.f);
    q1 = (int8_t)(int)h;
    q0 = (int8_t)(int)l;
}

// ---- fused prep: count + scan + scatter + rowmax reset (one CTA) -----------
__global__ __launch_bounds__(1024) void prep_all(const float* __restrict__ in) {
    __shared__ int scnt[32][16];
    __shared__ int wbase[32][16];
    __shared__ int tot[16];
    __shared__ int offs[16];

    const int tid = threadIdx.x, w = tid >> 5, lane = tid & 31;
    if (lane < 16) scnt[w][lane] = 0;
    for (int i = tid; i < 8 * BATCH; i += 1024) ((unsigned*)g_rowmax)[i] = 0u;
    __syncthreads();

    for (int b = tid; b < BATCH; b += 1024) {
        const float* oh = in + (size_t)b * INW + 128;
#pragma unroll
        for (int j = 0; j < NTYPE; j++) {
            int e = 0; float best = oh[j * NEXP];
#pragma unroll
            for (int m = 1; m < NEXP; m++) {
                float v = oh[j * NEXP + m];
                if (v > best) { best = v; e = m; }
            }
            g_idx[j][b] = e;
            atomicAdd(&scnt[w][j * 4 + e], 1);
        }
    }
    __syncthreads();

    if (tid < 16) {                     // per-bucket prefix over warps
        int s = 0;
#pragma unroll
        for (int w2 = 0; w2 < 32; w2++) { wbase[w2][tid] = s; s += scnt[w2][tid]; }
        tot[tid] = s;
    }
    __syncthreads();
    if (tid < 4) {                      // expert scan per type
        int s = 0;
#pragma unroll
        for (int e = 0; e < NEXP; e++) { g_off[tid][e] = s; offs[tid * 4 + e] = s; s += tot[tid * 4 + e]; }
        g_off[tid][NEXP] = s;
    }
    __syncthreads();
    if (tid < 16) {
        int base = offs[tid];
#pragma unroll
        for (int w2 = 0; w2 < 32; w2++) wbase[w2][tid] += base;
    }
    __syncthreads();

    for (int b = tid; b < BATCH; b += 1024) {
#pragma unroll
        for (int j = 0; j < NTYPE; j++) {
            int e = g_idx[j][b];
            int p = atomicAdd(&wbase[w][j * 4 + e], 1);
            g_order[j][p] = b;
        }
    }
}

// ---- fused weight quant: per-CTA (matrix, expert, 128-col strip) -----------
// pass 1: per-col max over K (coalesced row reads); pass 2: quantize +
// smem transpose -> [e][n][K] int8 pairs, 16B stores.
__global__ __launch_bounds__(256) void wprep(
    const float* __restrict__ W00, const float* __restrict__ W10,
    const float* __restrict__ W20, const float* __restrict__ W30,
    const float* __restrict__ W01, const float* __restrict__ W11,
    const float* __restrict__ W21, const float* __restrict__ W31)
{
    const int m = blockIdx.z;
    const float* src; int K, qoff, swoff;
    switch (m) {
        case 0: src = W00; K =   32; qoff = OFF_W00; swoff = 0 * 2048; break;
        case 1: src = W10; K =   32; qoff = OFF_W10; swoff = 1 * 2048; break;
        case 2: src = W20; K =   32; qoff = OFF_W20; swoff = 2 * 2048; break;
        case 3: src = W30; K =   32; qoff = OFF_W30; swoff = 3 * 2048; break;
        case 4: src = W01; K =  512; qoff = OFF_W01; swoff = 4 * 2048; break;
        case 5: src = W11; K = 1024; qoff = OFF_W11; swoff = 5 * 2048; break;
        case 6: src = W21; K = 1024; qoff = OFF_W21; swoff = 6 * 2048; break;
        default: src = W31; K = 1024; qoff = OFF_W31; swoff = 7 * 2048; break;
    }
    const int e  = blockIdx.y;
    const int n0 = blockIdx.x * 128;
    const int tid = threadIdx.x;
    const int tx = tid & 127, ty = tid >> 7;
    const float* s = src + (size_t)e * K * 512;

    __shared__ float smax[2][128];
    __shared__ float sinv[128];
    __shared__ __align__(16) int8_t tq1[128][16];
    __shared__ __align__(16) int8_t tq0[128][16];

    float mx = 0.f;
    for (int k = ty; k < K; k += 2)
        mx = fmaxf(mx, fabsf(s[(size_t)k * 512 + n0 + tx]));
    smax[ty][tx] = mx;
    __syncthreads();
    if (ty == 0) {
        float mm = fmaxf(smax[0][tx], smax[1][tx]);
        g_sW[swoff + e * 512 + n0 + tx] = mm / 16256.f;
        sinv[tx] = (mm > 0.f) ? 16256.f / mm : 0.f;
    }
    __syncthreads();

    for (int k0 = 0; k0 < K; k0 += 16) {
        float inv = sinv[tx];
#pragma unroll
        for (int r = 0; r < 8; r++) {
            int kk = ty * 8 + r;
            float v = s[(size_t)(k0 + kk) * 512 + n0 + tx] * inv;
            int8_t q1, q0; quant_pair(v, q1, q0);
            tq1[tx][kk] = q1;
            tq0[tx][kk] = q0;
        }
        __syncthreads();
        if (tid < 128) {
            *(uint4*)&g_wq1[((size_t)qoff) + ((size_t)(e * 512 + n0 + tid)) * K + k0] =
                *(uint4*)&tq1[tid][0];
        } else {
            int c = tid - 128;
            *(uint4*)&g_wq0[((size_t)qoff) + ((size_t)(e * 512 + n0 + c)) * K + k0] =
                *(uint4*)&tq0[c][0];
        }
        __syncthreads();
    }
}

// ---- feature quantization ---------------------------------------------------
__global__ void quant_feats(const float* __restrict__ in) {
    int w = (blockIdx.x * blockDim.x + threadIdx.x) >> 5;
    int lane = threadIdx.x & 31;
    if (w >= BATCH * 4) return;
    int b = w >> 2, j = w & 3;
    float v = in[(size_t)b * INW + j * 32 + lane];
    float a = fabsf(v);
#pragma unroll
    for (int d = 16; d; d >>= 1) a = fmaxf(a, __shfl_xor_sync(0xffffffffu, a, d));
    float inv = (a > 0.f) ? 16256.f / a : 0.f;
    int8_t q1, q0; quant_pair(v * inv, q1, q0);
    g_qf1[b * 128 + j * 32 + lane] = q1;
    g_qf0[b * 128 + j * 32 + lane] = q0;
    if (lane == 0) g_sfeat[j * BATCH + b] = a / 16256.f;
}

// quantize activations; selH >= 0 -> concat [X | H] with joint per-row scale
__global__ void quant_act(int selX, int selH, int slotX, int slotH, int Ktot) {
    int i = blockIdx.x * 256 + threadIdx.x;
    if (i >= BATCH * Ktot) return;
    int b = i / Ktot, c = i % Ktot;
    float rmx = __uint_as_float(g_rowmax[slotX][b]);
    if (selH >= 0) rmx = fmaxf(rmx, __uint_as_float(g_rowmax[slotH][b]));
    float v = (c < 512) ? act_ptr(selX)[(size_t)b * 512 + c]
                        : act_ptr(selH)[(size_t)b * 512 + (c - 512)];
    float inv = (rmx > 0.f) ? 16256.f / rmx : 0.f;
    int8_t q1, q0; quant_pair(v * inv, q1, q0);
    g_qa1[(size_t)b * Ktot + c] = q1;
    g_qa0[(size_t)b * Ktot + c] = q0;
    if (c == 0) g_sact[b] = rmx / 16256.f;
}

// ---- int8 grouped GEMM ------------------------------------------------------
__global__ __launch_bounds__(256, 2)
void gemm_i8(int aSel, int lda, int offA, int K, int sAoff,
             int woff, int swoff, const float* __restrict__ bias,
             int outSel, int rmslot, int jtype)
{
    extern __shared__ char sm[];
    int* srow = (int*)sm;
    char* tiles = sm + 512;

    const int e   = blockIdx.z;
    const int off = g_off[jtype][e];
    const int cnt = g_off[jtype][e + 1] - off;
    const int m0  = blockIdx.x * BM;
    if (m0 >= cnt) return;
    const int rows = min(BM, cnt - m0);
    const int n0   = blockIdx.y * BN;
    const int tid  = threadIdx.x;
    const int wid  = tid >> 5, lane = tid & 31;
    const int wm   = wid >> 1, wn = wid & 1;

    const int8_t* Aq1 = aSel ? g_qa1 : g_qf1;
    const int8_t* Aq0 = aSel ? g_qa0 : g_qf0;
    const float*  sA  = (aSel ? g_sact : g_sfeat) + sAoff;
    float* outF = act_ptr(outSel);
    unsigned* rowmax = g_rowmax[rmslot];

    for (int i = tid; i < BM; i += 256)
        srow[i] = (i < rows) ? g_order[jtype][off + m0 + i] : -1;
    __syncthreads();

    const int8_t* Wq1 = g_wq1 + woff + (size_t)(e * 512 + n0) * K;
    const int8_t* Wq0 = g_wq0 + woff + (size_t)(e * 512 + n0) * K;

    const int nchunk = (K + KB - 1) / KB;

    auto issue = [&](int c) {
        char* base = tiles + (c % 3) * SLOT;
        int k0 = c * KB;
#pragma unroll
        for (int i = 0; i < 4; i++) {            // A: 128 rows x 64B x 2 tensors
            int flat = i * 256 + tid;
            int tensor = flat >> 9, rem = flat & 511;
            int r = rem >> 2, seg = rem & 3;
            int rowid = srow[r];
            int k = k0 + seg * 16;
            const int8_t* src = tensor ? Aq0 : Aq1;
            const int8_t* gp = src + ((size_t)(rowid < 0 ? 0 : rowid) * lda + offA + k);
            uint32_t dst = smem_u32(base + tensor * 10240 + r * ROWB + seg * 16);
            int sz = (rowid >= 0 && k + 16 <= K) ? 16 : 0;
            CP_ASYNC16(dst, gp, sz);
        }
#pragma unroll
        for (int i = 0; i < 2; i++) {            // B: 64 rows x 64B x 2 tensors
            int flat = i * 256 + tid;
            int tensor = flat >> 8, rem = flat & 255;
            int r = rem >> 2, seg = rem & 3;
            int k = k0 + seg * 16;
            const int8_t* src = tensor ? Wq0 : Wq1;
            const int8_t* gp = src + ((size_t)r * K + k);
            uint32_t dst = smem_u32(base + 20480 + tensor * 5120 + r * ROWB + seg * 16);
            int sz = (k + 16 <= K) ? 16 : 0;
            CP_ASYNC16(dst, gp, sz);
        }
        CP_COMMIT();
    };

    int acc1[2][4][4], acc2[2][4][4];
#pragma unroll
    for (int mt = 0; mt < 2; mt++)
#pragma unroll
        for (int j = 0; j < 4; j++)
#pragma unroll
            for (int q = 0; q < 4; q++) { acc1[mt][j][q] = 0; acc2[mt][j][q] = 0; }

    issue(0);
    if (nchunk > 1) issue(1);

    // ldmatrix lane addressing
    const int aRow  = lane & 15;
    const int aHalf = lane >> 4;
    const int bRow  = ((lane >> 4) << 3) + (lane & 7);
    const int bHalf = (lane >> 3) & 1;

    for (int c = 0; c < nchunk; c++) {
        if (c + 1 < nchunk) asm volatile("cp.async.wait_group 1;" ::: "memory");
        else                asm volatile("cp.async.wait_group 0;" ::: "memory");
        __syncthreads();
        if (c + 2 < nchunk) issue(c + 2);

        char* base = tiles + (c % 3) * SLOT;
#pragma unroll
        for (int s = 0; s < 2; s++) {            // two k32 steps per chunk
            uint32_t a1[2][4], a0[2][4];
#pragma unroll
            for (int mt = 0; mt < 2; mt++) {
                uint32_t ra = smem_u32(base + (wm * 32 + mt * 16 + aRow) * ROWB
                                       + s * 32 + aHalf * 16);
                LDSM4(a1[mt], ra);
                LDSM4(a0[mt], ra + 10240);
            }
#pragma unroll
            for (int ng = 0; ng < 2; ng++) {
                int nrow = wn * 32 + ng * 16 + bRow;
                uint32_t rb = smem_u32(base + 20480 + nrow * ROWB
                                       + s * 32 + bHalf * 16);
                uint32_t b1[4], b0[4];
                LDSM4(b1, rb);
                LDSM4(b0, rb + 5120);
#pragma unroll
                for (int jt = 0; jt < 2; jt++) {
                    int j = ng * 2 + jt;
#pragma unroll
                    for (int mt = 0; mt < 2; mt++) {
                        MMA_S8(acc1[mt][j], a1[mt], b1[2 * jt], b1[2 * jt + 1]);
                        MMA_S8(acc2[mt][j], a1[mt], b0[2 * jt], b0[2 * jt + 1]);
                        MMA_S8(acc2[mt][j], a0[mt], b1[2 * jt], b1[2 * jt + 1]);
                    }
                }
            }
        }
    }

    // ---- epilogue: scale combine + bias + relu + scatter + rowmax ----------
    const float* sWl = g_sW + swoff + e * 512 + n0;
    const float* bl  = bias + e * 512 + n0;
    const int gid = lane >> 2, tig = lane & 3;
#pragma unroll
    for (int mt = 0; mt < 2; mt++) {
#pragma unroll
        for (int h = 0; h < 2; h++) {
            int rl = wm * 32 + mt * 16 + gid + h * 8;
            if (rl >= rows) continue;
            int gr = srow[rl];
            float sa = sA[gr];
            float rmx = 0.f;
#pragma unroll
            for (int j = 0; j < 4; j++) {
                int col = wn * 32 + j * 8 + tig * 2;
                int i0 = h * 2;
                float c0 = (float)acc1[mt][j][i0] * 16384.f
                         + (float)acc2[mt][j][i0] * 128.f;
                float c1 = (float)acc1[mt][j][i0 + 1] * 16384.f
                         + (float)acc2[mt][j][i0 + 1] * 128.f;
                float v0 = fmaxf(sa * sWl[col] * c0 + bl[col], 0.f);
                float v1 = fmaxf(sa * sWl[col + 1] * c1 + bl[col + 1], 0.f);
                rmx = fmaxf(rmx, fmaxf(v0, v1));
                float2 f2; f2.x = v0; f2.y = v1;
                *(float2*)(outF + (size_t)gr * 512 + n0 + col) = f2;
            }
            atomicMax(rowmax + gr, __float_as_uint(rmx));
        }
    }
}

// ---- head: out[b,0:8] = X[b] @ W3_2[e] + b3_2[e]  (no relu) ----------------
__global__ void head_kernel(const float* __restrict__ W,
                            const float* __restrict__ bias,
                            float* __restrict__ out)
{
    int warp_global = (blockIdx.x * blockDim.x + threadIdx.x) >> 5;
    int lane = threadIdx.x & 31;
    if (warp_global >= BATCH) return;
    int b = warp_global;
    int e = g_idx[3][b];
    const float* Wr = W + (size_t)e * HDIM * NOUT;
    const float* x  = g_actA + (size_t)b * HDIM;

    float s[NOUT];
#pragma unroll
    for (int o = 0; o < NOUT; o++) s[o] = 0.f;
    for (int k = lane; k < HDIM; k += 32) {
        float xv = x[k];
        const float* wr = Wr + (size_t)k * NOUT;
#pragma unroll
        for (int o = 0; o < NOUT; o++) s[o] += xv * wr[o];
    }
#pragma unroll
    for (int o = 0; o < NOUT; o++) {
#pragma unroll
        for (int d = 16; d > 0; d >>= 1)
            s[o] += __shfl_xor_sync(0xffffffffu, s[o], d);
    }
    if (lane < NOUT) out[(size_t)b * NOUT + lane] = s[lane] + bias[e * NOUT + lane];
}

// ---- launch -----------------------------------------------------------------
extern "C" void kernel_launch(void* const* d_in, const int* in_sizes, int n_in,
                              void* d_out, int out_size)
{
    const float* input = (const float*)d_in[0];
    const float* W00 = (const float*)d_in[1];  const float* b00 = (const float*)d_in[2];
    const float* W01 = (const float*)d_in[3];  const float* b01 = (const float*)d_in[4];
    const float* W10 = (const float*)d_in[5];  const float* b10 = (const float*)d_in[6];
    const float* W11 = (const float*)d_in[7];  const float* b11 = (const float*)d_in[8];
    const float* W20 = (const float*)d_in[9];  const float* b20 = (const float*)d_in[10];
    const float* W21 = (const float*)d_in[11]; const float* b21 = (const float*)d_in[12];
    const float* W30 = (const float*)d_in[13]; const float* b30 = (const float*)d_in[14];
    const float* W31 = (const float*)d_in[15]; const float* b31 = (const float*)d_in[16];
    const float* W32 = (const float*)d_in[17]; const float* b32 = (const float*)d_in[18];

    cudaFuncSetAttribute(gemm_i8, cudaFuncAttributeMaxDynamicSharedMemorySize, SMEM_TOT);

    // launch 0..2: prep / weight quant / feature quant
    prep_all<<<1, 1024>>>(input);
    wprep<<<dim3(4, 4, 8), 256>>>(W00, W10, W20, W30, W01, W11, W21, W31);
    quant_feats<<<(BATCH * 4 * 32 + 255) / 256, 256>>>(input);

    dim3 grid(BATCH / BM, HDIM / BN, NEXP);   // (64, 8, 4)
#define GEMM(aSel, lda, offA, K, sAoff, woff, swoff, bias, outSel, rms, jt) \
    gemm_i8<<<grid, 256, SMEM_TOT>>>(aSel, lda, offA, K, sAoff, woff, swoff, bias, outSel, rms, jt)

    // launch 3 (ncu capture target): L00 feats0 -> A (rowmax slot0)
    GEMM(0, 128,  0,   32, 0 * BATCH, OFF_W00, 0 * 2048, b00, 0, 0, 0);
    quant_act<<<(BATCH * 512 + 255) / 256, 256>>>(0, -1, 0, 0, 512);
    // L01: qa -> B (slot4)
    GEMM(1, 512,  0,  512, 0,         OFF_W01, 4 * 2048, b01, 1, 4, 0);
    // L10: feats1 -> H (slot1)
    GEMM(0, 128, 32,   32, 1 * BATCH, OFF_W10, 1 * 2048, b10, 2, 1, 1);
    quant_act<<<(BATCH * 1024 + 255) / 256, 256>>>(1, 2, 4, 1, 1024);
    // L11: qa -> A (slot5)
    GEMM(1, 1024, 0, 1024, 0,         OFF_W11, 5 * 2048, b11, 0, 5, 1);
    // L20: feats2 -> H (slot2)
    GEMM(0, 128, 64,   32, 2 * BATCH, OFF_W20, 2 * 2048, b20, 2, 2, 2);
    quant_act<<<(BATCH * 1024 + 255) / 256, 256>>>(0, 2, 5, 2, 1024);
    // L21: qa -> B (slot6)
    GEMM(1, 1024, 0, 1024, 0,         OFF_W21, 6 * 2048, b21, 1, 6, 2);
    // L30: feats3 -> H (slot3)
    GEMM(0, 128, 96,   32, 3 * BATCH, OFF_W30, 3 * 2048, b30, 2, 3, 3);
    quant_act<<<(BATCH * 1024 + 255) / 256, 256>>>(1, 2, 6, 3, 1024);
    // L31: qa -> A (slot7)
    GEMM(1, 1024, 0, 1024, 0,         OFF_W31, 7 * 2048, b31, 0, 7, 3);
    // head
    head_kernel<<<(BATCH * 32 + 255) / 256, 256>>>(W32, b32, (float*)d_out);

    (void)in_sizes; (void)n_in; (void)out_size;
}

// round 8
// speedup vs baseline: 2.4128x; 1.1880x over previous
#include <cuda_runtime.h>
#include <cstdint>

// ---------------------------------------------------------------------------
// CompositionalMlp: grouped-by-expert GEMM, int8 dual-word (15-bit) emulation
// R8: fused small-GEMM launch, per-row quant_act, leaner big-GEMM mainloop.
// ---------------------------------------------------------------------------

#define BATCH  8192
#define NEXP   4
#define NTYPE  4
#define HDIM   512
#define NOUT   8
#define INW    144

#define BM 128
#define BN 64
#define KB 64
#define ROWB 80                 // big-GEMM smem bytes per tile row
#define SLOT 30720              // A1(10240)+A0(10240)+B1(5120)+B0(5120)
#define SMEM_TOT (512 + 3 * SLOT)

// small-GEMM static smem layout (row stride 48B, conflict-free for ldmatrix)
#define RS   48
#define SA1  512
#define SA0  (512 + 6144)
#define SB1  (512 + 12288)
#define SB0  (512 + 15360)
#define SM_SMALL (512 + 18432)

// ---- scratch ----------------------------------------------------------------
__device__ int g_idx[NTYPE][BATCH];
__device__ int g_order[NTYPE][BATCH];
__device__ int g_off[NTYPE][NEXP + 1];

#define OFF_W00 0
#define OFF_W10 65536
#define OFF_W20 131072
#define OFF_W30 196608
#define OFF_W01 262144
#define OFF_W11 1310720
#define OFF_W21 3407872
#define OFF_W31 5505024
#define TOTAL_W 7602176
__device__ __align__(16) int8_t  g_wq1[TOTAL_W];
__device__ __align__(16) int8_t  g_wq0[TOTAL_W];
__device__ float   g_sW[8 * 2048];

__device__ __align__(16) int8_t  g_qf1[BATCH * 128];
__device__ __align__(16) int8_t  g_qf0[BATCH * 128];
__device__ float   g_sfeat[4 * BATCH];
__device__ __align__(16) int8_t  g_qa1[BATCH * 1024];
__device__ __align__(16) int8_t  g_qa0[BATCH * 1024];
__device__ float   g_sact[BATCH];
__device__ unsigned g_rowmax[8][BATCH];

__device__ float g_actX[BATCH * HDIM];
__device__ float g_actH1[BATCH * HDIM];
__device__ float g_actH2[BATCH * HDIM];
__device__ float g_actH3[BATCH * HDIM];

__device__ __forceinline__ float* act_ptr(int sel) {
    return sel == 0 ? g_actX : (sel == 1 ? g_actH1 : (sel == 2 ? g_actH2 : g_actH3));
}

// ---- PTX helpers ------------------------------------------------------------
__device__ __forceinline__ uint32_t smem_u32(const void* p) {
    return (uint32_t)__cvta_generic_to_shared(p);
}

#define CP_ASYNC16(dst, src, sz) \
    asm volatile("cp.async.cg.shared.global [%0], [%1], 16, %2;" \
                 :: "r"(dst), "l"(src), "r"(sz) : "memory")
#define CP_COMMIT() asm volatile("cp.async.commit_group;" ::: "memory")

#define LDSM4(r, addr)                                                        \
    asm volatile("ldmatrix.sync.aligned.m8n8.x4.shared.b16 {%0,%1,%2,%3},[%4];" \
                 : "=r"((r)[0]), "=r"((r)[1]), "=r"((r)[2]), "=r"((r)[3])     \
                 : "r"(addr))

#define MMA_S8(d, a, b0, b1)                                                  \
    asm volatile("mma.sync.aligned.m16n8k32.row.col.s32.s8.s8.s32 "           \
                 "{%0,%1,%2,%3},{%4,%5,%6,%7},{%8,%9},{%0,%1,%2,%3};"         \
                 : "+r"((d)[0]), "+r"((d)[1]), "+r"((d)[2]), "+r"((d)[3])     \
                 : "r"((a)[0]), "r"((a)[1]), "r"((a)[2]), "r"((a)[3]),        \
                   "r"(b0), "r"(b1))

__device__ __forceinline__ void quant_pair(float x, int8_t& q1, int8_t& q0) {
    float h = rintf(x * (1.f / 128.f));
    h = fminf(fmaxf(h, -127.f), 127.f);
    float l = rintf(x - 128.f * h);
    l = fminf(fmaxf(l, -127.f), 127.f);
    q1 = (int8_t)(int)h;
    q0 = (int8_t)(int)l;
}

// ---- fused prep: count + scan + scatter + rowmax reset (one CTA) -----------
__global__ __launch_bounds__(1024) void prep_all(const float* __restrict__ in) {
    __shared__ int scnt[32][16];
    __shared__ int wbase[32][16];
    __shared__ int tot[16];
    __shared__ int offs[16];

    const int tid = threadIdx.x, w = tid >> 5, lane = tid & 31;
    if (lane < 16) scnt[w][lane] = 0;
    for (int i = tid; i < 8 * BATCH; i += 1024) ((unsigned*)g_rowmax)[i] = 0u;
    __syncthreads();

    for (int b = tid; b < BATCH; b += 1024) {
        const float* oh = in + (size_t)b * INW + 128;
#pragma unroll
        for (int j = 0; j < NTYPE; j++) {
            int e = 0; float best = oh[j * NEXP];
#pragma unroll
            for (int m = 1; m < NEXP; m++) {
                float v = oh[j * NEXP + m];
                if (v > best) { best = v; e = m; }
            }
            g_idx[j][b] = e;
            atomicAdd(&scnt[w][j * 4 + e], 1);
        }
    }
    __syncthreads();

    if (tid < 16) {
        int s = 0;
#pragma unroll
        for (int w2 = 0; w2 < 32; w2++) { wbase[w2][tid] = s; s += scnt[w2][tid]; }
        tot[tid] = s;
    }
    __syncthreads();
    if (tid < 4) {
        int s = 0;
#pragma unroll
        for (int e = 0; e < NEXP; e++) { g_off[tid][e] = s; offs[tid * 4 + e] = s; s += tot[tid * 4 + e]; }
        g_off[tid][NEXP] = s;
    }
    __syncthreads();
    if (tid < 16) {
        int base = offs[tid];
#pragma unroll
        for (int w2 = 0; w2 < 32; w2++) wbase[w2][tid] += base;
    }
    __syncthreads();

    for (int b = tid; b < BATCH; b += 1024) {
#pragma unroll
        for (int j = 0; j < NTYPE; j++) {
            int e = g_idx[j][b];
            int p = atomicAdd(&wbase[w][j * 4 + e], 1);
            g_order[j][p] = b;
        }
    }
}

// ---- fused weight quant ------------------------------------------------------
__global__ __launch_bounds__(256) void wprep(
    const float* __restrict__ W00, const float* __restrict__ W10,
    const float* __restrict__ W20, const float* __restrict__ W30,
    const float* __restrict__ W01, const float* __restrict__ W11,
    const float* __restrict__ W21, const float* __restrict__ W31)
{
    const int m = blockIdx.z;
    const float* src; int K, qoff, swoff;
    switch (m) {
        case 0: src = W00; K =   32; qoff = OFF_W00; swoff = 0 * 2048; break;
        case 1: src = W10; K =   32; qoff = OFF_W10; swoff = 1 * 2048; break;
        case 2: src = W20; K =   32; qoff = OFF_W20; swoff = 2 * 2048; break;
        case 3: src = W30; K =   32; qoff = OFF_W30; swoff = 3 * 2048; break;
        case 4: src = W01; K =  512; qoff = OFF_W01; swoff = 4 * 2048; break;
        case 5: src = W11; K = 1024; qoff = OFF_W11; swoff = 5 * 2048; break;
        case 6: src = W21; K = 1024; qoff = OFF_W21; swoff = 6 * 2048; break;
        default: src = W31; K = 1024; qoff = OFF_W31; swoff = 7 * 2048; break;
    }
    const int e  = blockIdx.y;
    const int n0 = blockIdx.x * 128;
    const int tid = threadIdx.x;
    const int tx = tid & 127, ty = tid >> 7;
    const float* s = src + (size_t)e * K * 512;

    __shared__ float smax[2][128];
    __shared__ float sinv[128];
    __shared__ __align__(16) int8_t tq1[128][16];
    __shared__ __align__(16) int8_t tq0[128][16];

    float mx = 0.f;
    for (int k = ty; k < K; k += 2)
        mx = fmaxf(mx, fabsf(s[(size_t)k * 512 + n0 + tx]));
    smax[ty][tx] = mx;
    __syncthreads();
    if (ty == 0) {
        float mm = fmaxf(smax[0][tx], smax[1][tx]);
        g_sW[swoff + e * 512 + n0 + tx] = mm / 16256.f;
        sinv[tx] = (mm > 0.f) ? 16256.f / mm : 0.f;
    }
    __syncthreads();

    for (int k0 = 0; k0 < K; k0 += 16) {
        float inv = sinv[tx];
#pragma unroll
        for (int r = 0; r < 8; r++) {
            int kk = ty * 8 + r;
            float v = s[(size_t)(k0 + kk) * 512 + n0 + tx] * inv;
            int8_t q1, q0; quant_pair(v, q1, q0);
            tq1[tx][kk] = q1;
            tq0[tx][kk] = q0;
        }
        __syncthreads();
        if (tid < 128) {
            *(uint4*)&g_wq1[((size_t)qoff) + ((size_t)(e * 512 + n0 + tid)) * K + k0] =
                *(uint4*)&tq1[tid][0];
        } else {
            int c = tid - 128;
            *(uint4*)&g_wq0[((size_t)qoff) + ((size_t)(e * 512 + n0 + c)) * K + k0] =
                *(uint4*)&tq0[c][0];
        }
        __syncthreads();
    }
}

// ---- feature quantization ---------------------------------------------------
__global__ void quant_feats(const float* __restrict__ in) {
    int w = (blockIdx.x * blockDim.x + threadIdx.x) >> 5;
    int lane = threadIdx.x & 31;
    if (w >= BATCH * 4) return;
    int b = w >> 2, j = w & 3;
    float v = in[(size_t)b * INW + j * 32 + lane];
    float a = fabsf(v);
#pragma unroll
    for (int d = 16; d; d >>= 1) a = fmaxf(a, __shfl_xor_sync(0xffffffffu, a, d));
    float inv = (a > 0.f) ? 16256.f / a : 0.f;
    int8_t q1, q0; quant_pair(v * inv, q1, q0);
    g_qf1[b * 128 + j * 32 + lane] = q1;
    g_qf0[b * 128 + j * 32 + lane] = q0;
    if (lane == 0) g_sfeat[j * BATCH + b] = a / 16256.f;
}

// ---- activation quantization: one block per batch row -----------------------
__global__ __launch_bounds__(256) void quant_act(int selH, int slotX, int slotH, int Ktot) {
    const int b = blockIdx.x;
    const int t = threadIdx.x;
    __shared__ float sinv;
    if (t == 0) {
        float rmx = __uint_as_float(g_rowmax[slotX][b]);
        if (selH >= 0) rmx = fmaxf(rmx, __uint_as_float(g_rowmax[slotH][b]));
        g_sact[b] = rmx / 16256.f;
        sinv = (rmx > 0.f) ? 16256.f / rmx : 0.f;
    }
    __syncthreads();
    int c4 = t * 4;
    if (c4 >= Ktot) return;
    const float* srcp = (c4 < 512) ? (g_actX + (size_t)b * 512 + c4)
                                   : (act_ptr(selH) + (size_t)b * 512 + (c4 - 512));
    float4 v = *(const float4*)srcp;
    float inv = sinv;
    int8_t q1[4], q0[4];
    quant_pair(v.x * inv, q1[0], q0[0]);
    quant_pair(v.y * inv, q1[1], q0[1]);
    quant_pair(v.z * inv, q1[2], q0[2]);
    quant_pair(v.w * inv, q1[3], q0[3]);
    *(uint32_t*)&g_qa1[(size_t)b * Ktot + c4] = *(uint32_t*)q1;
    *(uint32_t*)&g_qa0[(size_t)b * Ktot + c4] = *(uint32_t*)q0;
}

// ---- fused small GEMMs (K=32): all 4 module types in one launch -------------
__global__ __launch_bounds__(256, 2)
void gemm_small(const float* __restrict__ b00, const float* __restrict__ b10,
                const float* __restrict__ b20, const float* __restrict__ b30)
{
    __shared__ __align__(16) char sm[SM_SMALL];
    int* srow = (int*)sm;

    const int j = blockIdx.z >> 2;
    const int e = blockIdx.z & 3;
    const int off = g_off[j][e];
    const int cnt = g_off[j][e + 1] - off;
    const int m0  = blockIdx.x * BM;
    if (m0 >= cnt) return;
    const int rows = min(BM, cnt - m0);
    const int n0   = blockIdx.y * BN;
    const int tid  = threadIdx.x;
    const int wid  = tid >> 5, lane = tid & 31;
    const int wm   = wid >> 1, wn = wid & 1;

    const float* bias = (j == 0) ? b00 : (j == 1) ? b10 : (j == 2) ? b20 : b30;
    float* outF = (j == 0) ? g_actX : (j == 1) ? g_actH1 : (j == 2) ? g_actH2 : g_actH3;
    const float* sA = g_sfeat + j * BATCH;
    unsigned* rowmax = g_rowmax[j];
    const int woff = j * 65536, swoff = j * 2048;
    const int offA = j * 32;

    for (int i = tid; i < BM; i += 256)
        srow[i] = (i < rows) ? g_order[j][off + m0 + i] : -1;
    __syncthreads();

    // ---- loads: A 128x32 x2 tensors, B 64x32 x2 tensors ----
#pragma unroll
    for (int i = 0; i < 2; i++) {
        int flat = i * 256 + tid;            // 0..511
        int tensor = flat >> 8, rem = flat & 255;
        int r = rem >> 1, seg = rem & 1;
        int rowid = srow[r];
        const int8_t* src = (tensor ? g_qf0 : g_qf1)
                          + (size_t)(rowid < 0 ? 0 : rowid) * 128 + offA + seg * 16;
        uint32_t dst = smem_u32(sm + (tensor ? SA0 : SA1) + r * RS + seg * 16);
        CP_ASYNC16(dst, src, (rowid >= 0) ? 16 : 0);
    }
    {
        int tensor = tid >> 7, rem = tid & 127;
        int r = rem >> 1, seg = rem & 1;
        const int8_t* src = (tensor ? g_wq0 : g_wq1) + woff
                          + (size_t)(e * 512 + n0 + r) * 32 + seg * 16;
        uint32_t dst = smem_u32(sm + (tensor ? SB0 : SB1) + r * RS + seg * 16);
        CP_ASYNC16(dst, src, 16);
    }
    CP_COMMIT();

    int acc1[2][4][4], acc2[2][4][4];
#pragma unroll
    for (int mt = 0; mt < 2; mt++)
#pragma unroll
        for (int q = 0; q < 4; q++)
#pragma unroll
            for (int x = 0; x < 4; x++) { acc1[mt][q][x] = 0; acc2[mt][q][x] = 0; }

    asm volatile("cp.async.wait_group 0;" ::: "memory");
    __syncthreads();

    const int aRow  = lane & 15;
    const int aHalf = lane >> 4;
    const int bRow  = ((lane >> 4) << 3) + (lane & 7);
    const int bHalf = (lane >> 3) & 1;

    uint32_t a1[2][4], a0[2][4];
#pragma unroll
    for (int mt = 0; mt < 2; mt++) {
        uint32_t ra = smem_u32(sm + SA1 + (wm * 32 + mt * 16 + aRow) * RS + aHalf * 16);
        LDSM4(a1[mt], ra);
        LDSM4(a0[mt], ra + (SA0 - SA1));
    }
#pragma unroll
    for (int ng = 0; ng < 2; ng++) {
        uint32_t rb = smem_u32(sm + SB1 + (wn * 32 + ng * 16 + bRow) * RS + bHalf * 16);
        uint32_t b1[4], b0[4];
        LDSM4(b1, rb);
        LDSM4(b0, rb + (SB0 - SB1));
#pragma unroll
        for (int jt = 0; jt < 2; jt++) {
            int jj = ng * 2 + jt;
#pragma unroll
            for (int mt = 0; mt < 2; mt++) {
                MMA_S8(acc1[mt][jj], a1[mt], b1[2 * jt], b1[2 * jt + 1]);
                MMA_S8(acc2[mt][jj], a1[mt], b0[2 * jt], b0[2 * jt + 1]);
                MMA_S8(acc2[mt][jj], a0[mt], b1[2 * jt], b1[2 * jt + 1]);
            }
        }
    }

    // ---- epilogue ----
    const float* sWl = g_sW + swoff + e * 512 + n0;
    const float* bl  = bias + e * 512 + n0;
    const int gid = lane >> 2, tig = lane & 3;
#pragma unroll
    for (int mt = 0; mt < 2; mt++) {
#pragma unroll
        for (int h = 0; h < 2; h++) {
            int rl = wm * 32 + mt * 16 + gid + h * 8;
            if (rl >= rows) continue;
            int gr = srow[rl];
            float sa = sA[gr];
            float rmx = 0.f;
#pragma unroll
            for (int jq = 0; jq < 4; jq++) {
                int col = wn * 32 + jq * 8 + tig * 2;
                int i0 = h * 2;
                float c0 = (float)acc1[mt][jq][i0] * 16384.f + (float)acc2[mt][jq][i0] * 128.f;
                float c1 = (float)acc1[mt][jq][i0 + 1] * 16384.f + (float)acc2[mt][jq][i0 + 1] * 128.f;
                float v0 = fmaxf(sa * sWl[col] * c0 + bl[col], 0.f);
                float v1 = fmaxf(sa * sWl[col + 1] * c1 + bl[col + 1], 0.f);
                rmx = fmaxf(rmx, fmaxf(v0, v1));
                float2 f2; f2.x = v0; f2.y = v1;
                *(float2*)(outF + (size_t)gr * 512 + n0 + col) = f2;
            }
            atomicMax(rowmax + gr, __float_as_uint(rmx));
        }
    }
}

// ---- big int8 grouped GEMM (K = 512 / 1024) ---------------------------------
__global__ __launch_bounds__(256, 2)
void gemm_i8(int K, int woff, int swoff, const float* __restrict__ bias,
             int rmslot, int jtype)
{
    extern __shared__ char sm[];
    int* srow = (int*)sm;
    char* tiles = sm + 512;

    const int e   = blockIdx.z;
    const int off = g_off[jtype][e];
    const int cnt = g_off[jtype][e + 1] - off;
    const int m0  = blockIdx.x * BM;
    if (m0 >= cnt) return;
    const int rows = min(BM, cnt - m0);
    const int n0   = blockIdx.y * BN;
    const int tid  = threadIdx.x;
    const int wid  = tid >> 5, lane = tid & 31;
    const int wm   = wid >> 1, wn = wid & 1;

    const float* sA = g_sact;
    float* outF = g_actX;
    unsigned* rowmax = g_rowmax[rmslot];

    for (int i = tid; i < BM; i += 256)
        srow[i] = (i < rows) ? g_order[jtype][off + m0 + i] : -1;
    __syncthreads();

    // ---- precompute per-thread cp.async roles --------------------------------
    const int8_t* psA[4]; uint32_t odA[4]; int szA[4];
#pragma unroll
    for (int i = 0; i < 4; i++) {
        int flat = i * 256 + tid;
        int tensor = flat >> 9, rem = flat & 511;
        int r = rem >> 2, seg = rem & 3;
        int rowid = srow[r];
        psA[i] = (tensor ? g_qa0 : g_qa1)
               + (size_t)(rowid < 0 ? 0 : rowid) * K + seg * 16;
        odA[i] = tensor * 10240 + r * ROWB + seg * 16;
        szA[i] = (rowid >= 0) ? 16 : 0;
    }
    const int8_t* psB[2]; uint32_t odB[2];
#pragma unroll
    for (int i = 0; i < 2; i++) {
        int flat = i * 256 + tid;
        int tensor = flat >> 8, rem = flat & 255;
        int r = rem >> 2, seg = rem & 3;
        psB[i] = (tensor ? g_wq0 : g_wq1) + woff
               + (size_t)(e * 512 + n0 + r) * K + seg * 16;
        odB[i] = 20480 + tensor * 5120 + r * ROWB + seg * 16;
    }
    const uint32_t tilesU = smem_u32(tiles);

    const int nchunk = K / KB;
    int isl = 0;                           // issue slot (rotates 0..2)

    auto issue = [&]() {
        uint32_t base = tilesU + isl * SLOT;
#pragma unroll
        for (int i = 0; i < 4; i++) {
            CP_ASYNC16(base + odA[i], psA[i], szA[i]);
            psA[i] += KB;
        }
#pragma unroll
        for (int i = 0; i < 2; i++) {
            CP_ASYNC16(base + odB[i], psB[i], 16);
            psB[i] += KB;
        }
        CP_COMMIT();
        isl = (isl == 2) ? 0 : isl + 1;
    };

    int acc1[2][4][4], acc2[2][4][4];
#pragma unroll
    for (int mt = 0; mt < 2; mt++)
#pragma unroll
        for (int q = 0; q < 4; q++)
#pragma unroll
            for (int x = 0; x < 4; x++) { acc1[mt][q][x] = 0; acc2[mt][q][x] = 0; }

    issue();
    issue();

    const int aRow  = lane & 15;
    const int aHalf = lane >> 4;
    const int bRow  = ((lane >> 4) << 3) + (lane & 7);
    const int bHalf = (lane >> 3) & 1;

    int csl = 0;
    for (int c = 0; c < nchunk; c++) {
        if (c + 1 < nchunk) asm volatile("cp.async.wait_group 1;" ::: "memory");
        else                asm volatile("cp.async.wait_group 0;" ::: "memory");
        __syncthreads();
        if (c + 2 < nchunk) issue();

        uint32_t base = tilesU + csl * SLOT;
        csl = (csl == 2) ? 0 : csl + 1;
#pragma unroll
        for (int s = 0; s < 2; s++) {
            uint32_t a1[2][4], a0[2][4];
#pragma unroll
            for (int mt = 0; mt < 2; mt++) {
                uint32_t ra = base + (wm * 32 + mt * 16 + aRow) * ROWB + s * 32 + aHalf * 16;
                LDSM4(a1[mt], ra);
                LDSM4(a0[mt], ra + 10240);
            }
#pragma unroll
            for (int ng = 0; ng < 2; ng++) {
                uint32_t rb = base + 20480 + (wn * 32 + ng * 16 + bRow) * ROWB + s * 32 + bHalf * 16;
                uint32_t b1[4], b0[4];
                LDSM4(b1, rb);
                LDSM4(b0, rb + 5120);
#pragma unroll
                for (int jt = 0; jt < 2; jt++) {
                    int jj = ng * 2 + jt;
#pragma unroll
                    for (int mt = 0; mt < 2; mt++) {
                        MMA_S8(acc1[mt][jj], a1[mt], b1[2 * jt], b1[2 * jt + 1]);
                        MMA_S8(acc2[mt][jj], a1[mt], b0[2 * jt], b0[2 * jt + 1]);
                        MMA_S8(acc2[mt][jj], a0[mt], b1[2 * jt], b1[2 * jt + 1]);
                    }
                }
            }
        }
    }

    // ---- epilogue ----
    const float* sWl = g_sW + swoff + e * 512 + n0;
    const float* bl  = bias + e * 512 + n0;
    const int gid = lane >> 2, tig = lane & 3;
#pragma unroll
    for (int mt = 0; mt < 2; mt++) {
#pragma unroll
        for (int h = 0; h < 2; h++) {
            int rl = wm * 32 + mt * 16 + gid + h * 8;
            if (rl >= rows) continue;
            int gr = srow[rl];
            float sa = sA[gr];
            float rmx = 0.f;
#pragma unroll
            for (int jq = 0; jq < 4; jq++) {
                int col = wn * 32 + jq * 8 + tig * 2;
                int i0 = h * 2;
                float c0 = (float)acc1[mt][jq][i0] * 16384.f + (float)acc2[mt][jq][i0] * 128.f;
                float c1 = (float)acc1[mt][jq][i0 + 1] * 16384.f + (float)acc2[mt][jq][i0 + 1] * 128.f;
                float v0 = fmaxf(sa * sWl[col] * c0 + bl[col], 0.f);
                float v1 = fmaxf(sa * sWl[col + 1] * c1 + bl[col + 1], 0.f);
                rmx = fmaxf(rmx, fmaxf(v0, v1));
                float2 f2; f2.x = v0; f2.y = v1;
                *(float2*)(outF + (size_t)gr * 512 + n0 + col) = f2;
            }
            atomicMax(rowmax + gr, __float_as_uint(rmx));
        }
    }
}

// ---- head -------------------------------------------------------------------
__global__ void head_kernel(const float* __restrict__ W,
                            const float* __restrict__ bias,
                            float* __restrict__ out)
{
    int warp_global = (blockIdx.x * blockDim.x + threadIdx.x) >> 5;
    int lane = threadIdx.x & 31;
    if (warp_global >= BATCH) return;
    int b = warp_global;
    int e = g_idx[3][b];
    const float* Wr = W + (size_t)e * HDIM * NOUT;
    const float* x  = g_actX + (size_t)b * HDIM;

    float s[NOUT];
#pragma unroll
    for (int o = 0; o < NOUT; o++) s[o] = 0.f;
    for (int k = lane; k < HDIM; k += 32) {
        float xv = x[k];
        const float* wr = Wr + (size_t)k * NOUT;
#pragma unroll
        for (int o = 0; o < NOUT; o++) s[o] += xv * wr[o];
    }
#pragma unroll
    for (int o = 0; o < NOUT; o++) {
#pragma unroll
        for (int d = 16; d > 0; d >>= 1)
            s[o] += __shfl_xor_sync(0xffffffffu, s[o], d);
    }
    if (lane < NOUT) out[(size_t)b * NOUT + lane] = s[lane] + bias[e * NOUT + lane];
}

// ---- launch -----------------------------------------------------------------
extern "C" void kernel_launch(void* const* d_in, const int* in_sizes, int n_in,
                              void* d_out, int out_size)
{
    const float* input = (const float*)d_in[0];
    const float* W00 = (const float*)d_in[1];  const float* b00 = (const float*)d_in[2];
    const float* W01 = (const float*)d_in[3];  const float* b01 = (const float*)d_in[4];
    const float* W10 = (const float*)d_in[5];  const float* b10 = (const float*)d_in[6];
    const float* W11 = (const float*)d_in[7];  const float* b11 = (const float*)d_in[8];
    const float* W20 = (const float*)d_in[9];  const float* b20 = (const float*)d_in[10];
    const float* W21 = (const float*)d_in[11]; const float* b21 = (const float*)d_in[12];
    const float* W30 = (const float*)d_in[13]; const float* b30 = (const float*)d_in[14];
    const float* W31 = (const float*)d_in[15]; const float* b31 = (const float*)d_in[16];
    const float* W32 = (const float*)d_in[17]; const float* b32 = (const float*)d_in[18];

    cudaFuncSetAttribute(gemm_i8, cudaFuncAttributeMaxDynamicSharedMemorySize, SMEM_TOT);

    prep_all<<<1, 1024>>>(input);                                     // 0
    wprep<<<dim3(4, 4, 8), 256>>>(W00, W10, W20, W30, W01, W11, W21, W31); // 1
    quant_feats<<<(BATCH * 4 * 32 + 255) / 256, 256>>>(input);        // 2

    // 3 (ncu capture target): all four K=32 expert-GEMMs in one launch
    gemm_small<<<dim3(BATCH / BM, HDIM / BN, 16), 256>>>(b00, b10, b20, b30);

    dim3 grid(BATCH / BM, HDIM / BN, NEXP);
    quant_act<<<BATCH, 256>>>(-1, 0, 0, 512);                                     // 4
    gemm_i8<<<grid, 256, SMEM_TOT>>>( 512, OFF_W01, 4 * 2048, b01, 4, 0);         // 5
    quant_act<<<BATCH, 256>>>( 1, 4, 1, 1024);                                    // 6
    gemm_i8<<<grid, 256, SMEM_TOT>>>(1024, OFF_W11, 5 * 2048, b11, 5, 1);         // 7
    quant_act<<<BATCH, 256>>>( 2, 5, 2, 1024);                                    // 8
    gemm_i8<<<grid, 256, SMEM_TOT>>>(1024, OFF_W21, 6 * 2048, b21, 6, 2);         // 9
    quant_act<<<BATCH, 256>>>( 3, 6, 3, 1024);                                    // 10
    gemm_i8<<<grid, 256, SMEM_TOT>>>(1024, OFF_W31, 7 * 2048, b31, 7, 3);         // 11
    head_kernel<<<(BATCH * 32 + 255) / 256, 256>>>(W32, b32, (float*)d_out);      // 12

    (void)in_sizes; (void)n_in; (void)out_size;
}